// round 8
// baseline (speedup 1.0000x reference)
#include <cuda_runtime.h>
#include <math.h>

// Problem constants
#define Bsz 4
#define Tn  1024
#define Dm  1024
#define Hn  16
#define HSz 64
#define Ln  4
#define FFn 4096
#define Vn  32000
#define EPSf 1e-5f
#define BT  (Bsz*Tn)   // 4096
#define SCALE 0.125f   // HS^-0.5

// ---------------- scratch (device globals; allocation is forbidden) -------
__device__ float g_x[BT*Dm];          // residual stream        16 MB
__device__ float g_h[BT*Dm];          // layernorm output       16 MB
__device__ float g_qkv[BT*3*Dm];      // fused QKV              48 MB
__device__ float g_o[BT*Dm];          // attention output       16 MB
__device__ float g_ffn[BT*FFn];       // FFN activation         64 MB
__device__ float g_wt[Dm*3*Dm];       // transposed QKV weights 12 MB
__device__ float g_logits[BT*Vn];     // logits                524 MB
__device__ float g_nll[BT];

// ---------------- embedding ----------------------------------------------
__global__ void embed_kernel(const int* __restrict__ idx,
                             const float* __restrict__ tok,
                             const float* __restrict__ pos) {
    int gid = blockIdx.x * 256 + threadIdx.x;      // BT*Dm threads
    int bt = gid >> 10;
    int d  = gid & 1023;
    int t  = bt & (Tn - 1);
    g_x[gid] = tok[(size_t)idx[bt] * Dm + d] + pos[t * Dm + d];
}

// ---------------- layernorm (row = 1024, block = 256) ---------------------
__global__ void ln_kernel(const float* __restrict__ x,
                          const float* __restrict__ g,
                          const float* __restrict__ b,
                          float* __restrict__ out) {
    int row = blockIdx.x, tid = threadIdx.x;
    const float* xr = x + (size_t)row * Dm;
    float v[4]; float s = 0.f;
    #pragma unroll
    for (int i = 0; i < 4; i++) { v[i] = xr[tid + i*256]; s += v[i]; }
    __shared__ float red[256];
    red[tid] = s; __syncthreads();
    for (int st = 128; st > 0; st >>= 1) { if (tid < st) red[tid] += red[tid+st]; __syncthreads(); }
    float m = red[0] * (1.0f / Dm);
    __syncthreads();
    float sq = 0.f;
    #pragma unroll
    for (int i = 0; i < 4; i++) { float d = v[i] - m; sq += d * d; }
    red[tid] = sq; __syncthreads();
    for (int st = 128; st > 0; st >>= 1) { if (tid < st) red[tid] += red[tid+st]; __syncthreads(); }
    float inv = rsqrtf(red[0] * (1.0f / Dm) + EPSf);
    #pragma unroll
    for (int i = 0; i < 4; i++) {
        int d = tid + i*256;
        out[(size_t)row * Dm + d] = (v[i] - m) * inv * g[d] + b[d];
    }
}

// ---------------- QKV weight transpose: [H,D,HS] -> [D, 3*D] --------------
__global__ void wtrans_kernel(const float* __restrict__ Wq,
                              const float* __restrict__ Wk,
                              const float* __restrict__ Wv) {
    int gid = blockIdx.x * 256 + threadIdx.x;   // Dm*Dm threads
    int d = gid >> 10;
    int c = gid & 1023;        // c = h*HS + s
    int h = c >> 6, s = c & 63;
    int src = (h * Dm + d) * HSz + s;
    g_wt[(size_t)d * 3*Dm + c]          = Wq[src];
    g_wt[(size_t)d * 3*Dm + Dm + c]     = Wk[src];
    g_wt[(size_t)d * 3*Dm + 2*Dm + c]   = Wv[src];
}

// ---------------- SGEMM: C = A[M,K] @ B[K,N] (+bias)(+C)(relu) ------------
// 128x128 tile, BK=8, 256 threads, 8x8 microtile, double-buffered smem with
// register-staged global prefetch. M%128==0, N%128==0, K%16==0.
#define FLAG_RELU  1
#define FLAG_RESID 2
__global__ void __launch_bounds__(256) sgemm_kernel(
        const float* __restrict__ A, const float* __restrict__ B,
        const float* __restrict__ bias, float* __restrict__ C,
        int M, int N, int K, int flags) {
    __shared__ float As[2][8][128];
    __shared__ float Bs[2][8][128];
    int tid  = threadIdx.x;
    int brow = blockIdx.y * 128;
    int bcol = blockIdx.x * 128;
    int aRow = tid >> 1;            // 0..127
    int aCol = (tid & 1) * 4;       // 0 or 4
    int bRow = tid >> 5;            // 0..7
    int bCol = (tid & 31) * 4;      // 0..124
    int tr = (tid >> 4) * 8;        // 0..120 step 8
    int tc = (tid & 15) * 8;

    float acc[8][8];
    #pragma unroll
    for (int i = 0; i < 8; i++)
        #pragma unroll
        for (int j = 0; j < 8; j++) acc[i][j] = 0.f;

    const float* aSrc = A + (size_t)(brow + aRow) * K + aCol;
    const float* bSrc = B + (size_t)bRow * N + bcol + bCol;

    // prime buffer 0
    float4 av = *(const float4*)aSrc;
    float4 bv = *(const float4*)bSrc;
    As[0][aCol+0][aRow] = av.x; As[0][aCol+1][aRow] = av.y;
    As[0][aCol+2][aRow] = av.z; As[0][aCol+3][aRow] = av.w;
    *(float4*)&Bs[0][bRow][bCol] = bv;
    __syncthreads();

    int nk = K >> 3;
    for (int kb = 1; kb < nk; kb++) {
        // prefetch next slab into registers (in flight during compute)
        av = *(const float4*)(aSrc + (kb << 3));
        bv = *(const float4*)(bSrc + (size_t)(kb << 3) * N);
        int cur = (kb - 1) & 1;
        #pragma unroll
        for (int kk = 0; kk < 8; kk++) {
            float4 a0 = *(const float4*)&As[cur][kk][tr];
            float4 a1 = *(const float4*)&As[cur][kk][tr + 4];
            float4 b0 = *(const float4*)&Bs[cur][kk][tc];
            float4 b1 = *(const float4*)&Bs[cur][kk][tc + 4];
            float a[8] = {a0.x,a0.y,a0.z,a0.w,a1.x,a1.y,a1.z,a1.w};
            float bb[8] = {b0.x,b0.y,b0.z,b0.w,b1.x,b1.y,b1.z,b1.w};
            #pragma unroll
            for (int i = 0; i < 8; i++)
                #pragma unroll
                for (int j = 0; j < 8; j++) acc[i][j] += a[i] * bb[j];
        }
        int nxt = kb & 1;
        As[nxt][aCol+0][aRow] = av.x; As[nxt][aCol+1][aRow] = av.y;
        As[nxt][aCol+2][aRow] = av.z; As[nxt][aCol+3][aRow] = av.w;
        *(float4*)&Bs[nxt][bRow][bCol] = bv;
        __syncthreads();
    }
    {
        int cur = (nk - 1) & 1;
        #pragma unroll
        for (int kk = 0; kk < 8; kk++) {
            float4 a0 = *(const float4*)&As[cur][kk][tr];
            float4 a1 = *(const float4*)&As[cur][kk][tr + 4];
            float4 b0 = *(const float4*)&Bs[cur][kk][tc];
            float4 b1 = *(const float4*)&Bs[cur][kk][tc + 4];
            float a[8] = {a0.x,a0.y,a0.z,a0.w,a1.x,a1.y,a1.z,a1.w};
            float bb[8] = {b0.x,b0.y,b0.z,b0.w,b1.x,b1.y,b1.z,b1.w};
            #pragma unroll
            for (int i = 0; i < 8; i++)
                #pragma unroll
                for (int j = 0; j < 8; j++) acc[i][j] += a[i] * bb[j];
        }
    }

    #pragma unroll
    for (int i = 0; i < 8; i++) {
        size_t row = (size_t)(brow + tr + i);
        float* crow = C + row * N + bcol + tc;
        #pragma unroll
        for (int j = 0; j < 8; j++) {
            float v = acc[i][j];
            if (bias) v += bias[bcol + tc + j];
            if (flags & FLAG_RESID) v += crow[j];
            if (flags & FLAG_RELU)  v = fmaxf(v, 0.f);
            crow[j] = v;
        }
    }
}

// ---------------- attention scores: S = Q @ K^T * scale -------------------
// grid (T/64 [kt], T/64 [qt], B*H); 64x64 tile; skips upper-triangular tiles.
__global__ void __launch_bounds__(256) scores_kernel(float* __restrict__ attn) {
    int kt = blockIdx.x, qt = blockIdx.y;
    if (kt > qt) return;
    int bh = blockIdx.z;
    int b = bh >> 4, h = bh & 15;
    __shared__ float Qs[64][68];
    __shared__ float Ks[64][68];
    int tid = threadIdx.x;
    int lr = tid >> 4;           // 0..15
    int lc = (tid & 15) * 4;     // 0..60
    #pragma unroll
    for (int r = 0; r < 4; r++) {
        int row = r * 16 + lr;
        const float* qp = g_qkv + (size_t)(b*Tn + qt*64 + row) * (3*Dm) + h*HSz + lc;
        float4 qv = *(const float4*)qp;
        Qs[row][lc] = qv.x; Qs[row][lc+1] = qv.y; Qs[row][lc+2] = qv.z; Qs[row][lc+3] = qv.w;
        const float* kp = g_qkv + (size_t)(b*Tn + kt*64 + row) * (3*Dm) + Dm + h*HSz + lc;
        float4 kv = *(const float4*)kp;
        Ks[row][lc] = kv.x; Ks[row][lc+1] = kv.y; Ks[row][lc+2] = kv.z; Ks[row][lc+3] = kv.w;
    }
    __syncthreads();
    int tr = lr * 4, tc = lc;   // 4x4 microtile
    float acc[4][4] = {};
    #pragma unroll
    for (int kk = 0; kk < 64; kk++) {
        float a[4], bb[4];
        #pragma unroll
        for (int i = 0; i < 4; i++) a[i]  = Qs[tr + i][kk];
        #pragma unroll
        for (int j = 0; j < 4; j++) bb[j] = Ks[tc + j][kk];
        #pragma unroll
        for (int i = 0; i < 4; i++)
            #pragma unroll
            for (int j = 0; j < 4; j++) acc[i][j] += a[i] * bb[j];
    }
    float* outp = attn + (size_t)bh * Tn * Tn;
    #pragma unroll
    for (int i = 0; i < 4; i++)
        #pragma unroll
        for (int j = 0; j < 4; j++)
            outp[(size_t)(qt*64 + tr + i) * Tn + kt*64 + tc + j] = acc[i][j] * SCALE;
}

// ---------------- causal softmax in-place over d_out attn rows ------------
// grid (T [t], B*H); block 256
__global__ void __launch_bounds__(256) softmax_kernel(float* __restrict__ attn) {
    int t = blockIdx.x, bh = blockIdx.y, tid = threadIdx.x;
    float* row = attn + (size_t)bh * Tn * Tn + (size_t)t * Tn;
    int valid = t + 1;
    float v[4];
    float m = -1e30f;
    #pragma unroll
    for (int i = 0; i < 4; i++) {
        int j = tid + i*256;
        v[i] = row[j];
        if (j < valid) m = fmaxf(m, v[i]);
    }
    __shared__ float red[256];
    red[tid] = m; __syncthreads();
    for (int st = 128; st > 0; st >>= 1) { if (tid < st) red[tid] = fmaxf(red[tid], red[tid+st]); __syncthreads(); }
    m = red[0]; __syncthreads();
    float s = 0.f;
    #pragma unroll
    for (int i = 0; i < 4; i++) {
        int j = tid + i*256;
        float e = (j < valid) ? expf(v[i] - m) : 0.f;
        v[i] = e; s += e;
    }
    red[tid] = s; __syncthreads();
    for (int st = 128; st > 0; st >>= 1) { if (tid < st) red[tid] += red[tid+st]; __syncthreads(); }
    float inv = 1.0f / red[0];
    #pragma unroll
    for (int i = 0; i < 4; i++) row[tid + i*256] = v[i] * inv;
}

// ---------------- O = P @ V (causal k-loop) -------------------------------
// grid (T/64 [qt], B*H). NOTE: attn base is d_out+1 (4 mod 16 bytes), so the
// probability tile must be read with scalar (32-bit) loads, never float4.
__global__ void __launch_bounds__(256) av_kernel(const float* __restrict__ attn,
                                                 float* __restrict__ O) {
    int qt = blockIdx.x, bh = blockIdx.y;
    int b = bh >> 4, h = bh & 15;
    __shared__ float Ps[64][68];
    __shared__ float Vs[64][68];
    int tid = threadIdx.x;
    int lr = tid >> 4;
    int lc = (tid & 15) * 4;
    int tr = lr * 4, tc = lc;
    float acc[4][4] = {};
    const float* abase = attn + (size_t)bh * Tn * Tn;
    for (int kt = 0; kt <= qt; kt++) {
        #pragma unroll
        for (int r = 0; r < 4; r++) {
            int row = r * 16 + lr;
            const float* pp = abase + (size_t)(qt*64 + row) * Tn + kt*64 + lc;
            Ps[row][lc]   = pp[0];
            Ps[row][lc+1] = pp[1];
            Ps[row][lc+2] = pp[2];
            Ps[row][lc+3] = pp[3];
            const float* vp = g_qkv + (size_t)(b*Tn + kt*64 + row) * (3*Dm) + 2*Dm + h*HSz + lc;
            float4 vv = *(const float4*)vp;
            Vs[row][lc] = vv.x; Vs[row][lc+1] = vv.y; Vs[row][lc+2] = vv.z; Vs[row][lc+3] = vv.w;
        }
        __syncthreads();
        #pragma unroll
        for (int kk = 0; kk < 64; kk++) {
            float a[4], bb[4];
            #pragma unroll
            for (int i = 0; i < 4; i++) a[i]  = Ps[tr + i][kk];
            #pragma unroll
            for (int j = 0; j < 4; j++) bb[j] = Vs[kk][tc + j];
            #pragma unroll
            for (int i = 0; i < 4; i++)
                #pragma unroll
                for (int j = 0; j < 4; j++) acc[i][j] += a[i] * bb[j];
        }
        __syncthreads();
    }
    #pragma unroll
    for (int i = 0; i < 4; i++)
        #pragma unroll
        for (int j = 0; j < 4; j++)
            O[(size_t)(b*Tn + qt*64 + tr + i) * Dm + h*HSz + tc + j] = acc[i][j];
}

// ---------------- per-row NLL over 32000-way logits -----------------------
__global__ void __launch_bounds__(512) nll_kernel(const int* __restrict__ targets) {
    int row = blockIdx.x, tid = threadIdx.x;
    const float* lr = g_logits + (size_t)row * Vn;
    float m = -1e30f;
    for (int j = tid; j < Vn; j += 512) m = fmaxf(m, lr[j]);
    __shared__ float red[512];
    red[tid] = m; __syncthreads();
    for (int st = 256; st > 0; st >>= 1) { if (tid < st) red[tid] = fmaxf(red[tid], red[tid+st]); __syncthreads(); }
    m = red[0]; __syncthreads();
    float s = 0.f;
    for (int j = tid; j < Vn; j += 512) s += expf(lr[j] - m);
    red[tid] = s; __syncthreads();
    for (int st = 256; st > 0; st >>= 1) { if (tid < st) red[tid] += red[tid+st]; __syncthreads(); }
    if (tid == 0) {
        int tg = targets[row];
        g_nll[row] = -(lr[tg] - m - logf(red[0]));
    }
}

__global__ void __launch_bounds__(256) loss_reduce_kernel(float* __restrict__ out) {
    int tid = threadIdx.x;
    float s = 0.f;
    for (int i = tid; i < BT; i += 256) s += g_nll[i];
    __shared__ float red[256];
    red[tid] = s; __syncthreads();
    for (int st = 128; st > 0; st >>= 1) { if (tid < st) red[tid] += red[tid+st]; __syncthreads(); }
    if (tid == 0) out[0] = red[0] / (float)BT;
}

// ---------------- launch ---------------------------------------------------
extern "C" void kernel_launch(void* const* d_in, const int* in_sizes, int n_in,
                              void* d_out, int out_size) {
    const int*   idx     = (const int*)  d_in[0];
    const int*   targets = (const int*)  d_in[1];
    const float* tok     = (const float*)d_in[2];
    const float* pos     = (const float*)d_in[3];
    const float* ln1_g   = (const float*)d_in[4];
    const float* ln1_b   = (const float*)d_in[5];
    const float* Wq      = (const float*)d_in[6];
    const float* Wk      = (const float*)d_in[7];
    const float* Wv      = (const float*)d_in[8];
    const float* Wp      = (const float*)d_in[9];
    const float* bp      = (const float*)d_in[10];
    const float* ln2_g   = (const float*)d_in[11];
    const float* ln2_b   = (const float*)d_in[12];
    const float* W1      = (const float*)d_in[13];
    const float* b1      = (const float*)d_in[14];
    const float* W2      = (const float*)d_in[15];
    const float* b2      = (const float*)d_in[16];
    const float* lnf_g   = (const float*)d_in[17];
    const float* lnf_b   = (const float*)d_in[18];
    const float* Wlm     = (const float*)d_in[19];
    const float* blm     = (const float*)d_in[20];

    float* out = (float*)d_out;
    float* attn_all = out + 1;   // (loss, attn) flattened

    float *px, *ph, *pqkv, *po, *pffn, *pwt, *plogits;
    cudaGetSymbolAddress((void**)&px,      g_x);
    cudaGetSymbolAddress((void**)&ph,      g_h);
    cudaGetSymbolAddress((void**)&pqkv,    g_qkv);
    cudaGetSymbolAddress((void**)&po,      g_o);
    cudaGetSymbolAddress((void**)&pffn,    g_ffn);
    cudaGetSymbolAddress((void**)&pwt,     g_wt);
    cudaGetSymbolAddress((void**)&plogits, g_logits);

    embed_kernel<<<(BT*Dm)/256, 256>>>(idx, tok, pos);

    for (int l = 0; l < Ln; l++) {
        float* attn_l = attn_all + (size_t)l * Bsz * Hn * Tn * Tn;
        size_t woff = (size_t)l * Hn * Dm * HSz;

        ln_kernel<<<BT, 256>>>(px, ln1_g + l*Dm, ln1_b + l*Dm, ph);
        wtrans_kernel<<<(Dm*Dm)/256, 256>>>(Wq + woff, Wk + woff, Wv + woff);
        sgemm_kernel<<<dim3(3*Dm/128, BT/128), 256>>>(ph, pwt, nullptr, pqkv,
                                                      BT, 3*Dm, Dm, 0);
        scores_kernel<<<dim3(Tn/64, Tn/64, Bsz*Hn), 256>>>(attn_l);
        softmax_kernel<<<dim3(Tn, Bsz*Hn), 256>>>(attn_l);
        av_kernel<<<dim3(Tn/64, Bsz*Hn), 256>>>(attn_l, po);
        sgemm_kernel<<<dim3(Dm/128, BT/128), 256>>>(po, Wp + (size_t)l*Dm*Dm,
                                                    bp + l*Dm, px,
                                                    BT, Dm, Dm, FLAG_RESID);
        ln_kernel<<<BT, 256>>>(px, ln2_g + l*Dm, ln2_b + l*Dm, ph);
        sgemm_kernel<<<dim3(FFn/128, BT/128), 256>>>(ph, W1 + (size_t)l*Dm*FFn,
                                                     b1 + l*FFn, pffn,
                                                     BT, FFn, Dm, FLAG_RELU);
        sgemm_kernel<<<dim3(Dm/128, BT/128), 256>>>(pffn, W2 + (size_t)l*FFn*Dm,
                                                    b2 + l*Dm, px,
                                                    BT, Dm, FFn, FLAG_RESID);
    }

    ln_kernel<<<BT, 256>>>(px, lnf_g, lnf_b, ph);
    sgemm_kernel<<<dim3(Vn/128, BT/128), 256>>>(ph, Wlm, blm, plogits,
                                                BT, Vn, Dm, 0);
    nll_kernel<<<BT, 512>>>(targets);
    loss_reduce_kernel<<<1, 256>>>(out);
}

// round 11
// speedup vs baseline: 1.9733x; 1.9733x over previous
#include <cuda_runtime.h>
#include <cuda_bf16.h>
#include <math.h>
#include <stdint.h>

// Problem constants
#define Bsz 4
#define Tn  1024
#define Dm  1024
#define Hn  16
#define HSz 64
#define Ln  4
#define FFn 4096
#define Vn  32000
#define EPSf 1e-5f
#define BT  (Bsz*Tn)   // 4096
#define SCALE 0.125f   // HS^-0.5

// ---------------- scratch (device globals; allocation is forbidden) -------
__device__ float g_x[BT*Dm];              // residual stream        16 MB
__device__ float g_h[BT*Dm];              // layernorm output       16 MB
__device__ float g_qkv[BT*3*Dm];          // fused QKV              48 MB
__device__ float g_o[BT*Dm];              // attention output       16 MB
__device__ float g_ffn[BT*FFn];           // FFN activation         64 MB
__device__ float g_wt[Dm*3*Dm];           // transposed QKV weights 12 MB
__device__ float g_logits[(size_t)BT*Vn]; // logits                524 MB
__device__ float g_nll[BT];
__device__ __nv_bfloat16 g_hb[BT*Dm];               // bf16 LN-f out   8 MB
__device__ __nv_bfloat16 g_wlmb[(size_t)Vn*Dm];     // Wlm^T bf16     64 MB

// ---------------- embedding ----------------------------------------------
__global__ void embed_kernel(const int* __restrict__ idx,
                             const float* __restrict__ tok,
                             const float* __restrict__ pos) {
    int gid = blockIdx.x * 256 + threadIdx.x;      // BT*Dm threads
    int bt = gid >> 10;
    int d  = gid & 1023;
    int t  = bt & (Tn - 1);
    g_x[gid] = tok[(size_t)idx[bt] * Dm + d] + pos[t * Dm + d];
}

// ---------------- layernorm (row = 1024, block = 256) ---------------------
__global__ void ln_kernel(const float* __restrict__ x,
                          const float* __restrict__ g,
                          const float* __restrict__ b,
                          float* __restrict__ out) {
    int row = blockIdx.x, tid = threadIdx.x;
    const float* xr = x + (size_t)row * Dm;
    float v[4]; float s = 0.f;
    #pragma unroll
    for (int i = 0; i < 4; i++) { v[i] = xr[tid + i*256]; s += v[i]; }
    __shared__ float red[256];
    red[tid] = s; __syncthreads();
    for (int st = 128; st > 0; st >>= 1) { if (tid < st) red[tid] += red[tid+st]; __syncthreads(); }
    float m = red[0] * (1.0f / Dm);
    __syncthreads();
    float sq = 0.f;
    #pragma unroll
    for (int i = 0; i < 4; i++) { float d = v[i] - m; sq += d * d; }
    red[tid] = sq; __syncthreads();
    for (int st = 128; st > 0; st >>= 1) { if (tid < st) red[tid] += red[tid+st]; __syncthreads(); }
    float inv = rsqrtf(red[0] * (1.0f / Dm) + EPSf);
    #pragma unroll
    for (int i = 0; i < 4; i++) {
        int d = tid + i*256;
        out[(size_t)row * Dm + d] = (v[i] - m) * inv * g[d] + b[d];
    }
}

// ---------------- QKV weight transpose: [H,D,HS] -> [D, 3*D] --------------
__global__ void wtrans_kernel(const float* __restrict__ Wq,
                              const float* __restrict__ Wk,
                              const float* __restrict__ Wv) {
    int gid = blockIdx.x * 256 + threadIdx.x;   // Dm*Dm threads
    int d = gid >> 10;
    int c = gid & 1023;        // c = h*HS + s
    int h = c >> 6, s = c & 63;
    int src = (h * Dm + d) * HSz + s;
    g_wt[(size_t)d * 3*Dm + c]          = Wq[src];
    g_wt[(size_t)d * 3*Dm + Dm + c]     = Wk[src];
    g_wt[(size_t)d * 3*Dm + 2*Dm + c]   = Wv[src];
}

// ---------------- SGEMM (R6 known-good): single-buffered 128x128x8 --------
#define FLAG_RELU  1
#define FLAG_RESID 2
__global__ void __launch_bounds__(256) sgemm_kernel(
        const float* __restrict__ A, const float* __restrict__ B,
        const float* __restrict__ bias, float* __restrict__ C,
        int M, int N, int K, int flags) {
    __shared__ float As[8][128];
    __shared__ float Bs[8][128];
    int tid  = threadIdx.x;
    int brow = blockIdx.y * 128;
    int bcol = blockIdx.x * 128;
    int aRow = tid >> 1;            // 0..127
    int aCol = (tid & 1) * 4;       // 0 or 4
    int bRow = tid >> 5;            // 0..7
    int bCol = (tid & 31) * 4;      // 0..124
    int tr = (tid >> 4) * 8;        // 0..120 step 8
    int tc = (tid & 15) * 8;

    float acc[8][8];
    #pragma unroll
    for (int i = 0; i < 8; i++)
        #pragma unroll
        for (int j = 0; j < 8; j++) acc[i][j] = 0.f;

    const float* Aptr = A + (size_t)brow * K;
    const float* Bptr = B + bcol;

    for (int k0 = 0; k0 < K; k0 += 8) {
        float4 av = *(const float4*)(Aptr + (size_t)aRow * K + k0 + aCol);
        As[aCol+0][aRow] = av.x; As[aCol+1][aRow] = av.y;
        As[aCol+2][aRow] = av.z; As[aCol+3][aRow] = av.w;
        float4 bv = *(const float4*)(Bptr + (size_t)(k0 + bRow) * N + bCol);
        *(float4*)&Bs[bRow][bCol] = bv;
        __syncthreads();
        #pragma unroll
        for (int kk = 0; kk < 8; kk++) {
            float a[8], bb[8];
            #pragma unroll
            for (int i = 0; i < 8; i++) a[i]  = As[kk][tr + i];
            #pragma unroll
            for (int j = 0; j < 8; j++) bb[j] = Bs[kk][tc + j];
            #pragma unroll
            for (int i = 0; i < 8; i++)
                #pragma unroll
                for (int j = 0; j < 8; j++) acc[i][j] += a[i] * bb[j];
        }
        __syncthreads();
    }

    #pragma unroll
    for (int i = 0; i < 8; i++) {
        size_t row = (size_t)(brow + tr + i);
        float* crow = C + row * N + bcol + tc;
        #pragma unroll
        for (int j = 0; j < 8; j++) {
            float v = acc[i][j];
            if (bias) v += bias[bcol + tc + j];
            if (flags & FLAG_RESID) v += crow[j];
            if (flags & FLAG_RELU)  v = fmaxf(v, 0.f);
            crow[j] = v;
        }
    }
}

// ---------------- attention scores: S = Q @ K^T * scale -------------------
__global__ void __launch_bounds__(256) scores_kernel(float* __restrict__ attn) {
    int kt = blockIdx.x, qt = blockIdx.y;
    if (kt > qt) return;
    int bh = blockIdx.z;
    int b = bh >> 4, h = bh & 15;
    __shared__ float Qs[64][68];
    __shared__ float Ks[64][68];
    int tid = threadIdx.x;
    int lr = tid >> 4;           // 0..15
    int lc = (tid & 15) * 4;     // 0..60
    #pragma unroll
    for (int r = 0; r < 4; r++) {
        int row = r * 16 + lr;
        const float* qp = g_qkv + (size_t)(b*Tn + qt*64 + row) * (3*Dm) + h*HSz + lc;
        float4 qv = *(const float4*)qp;
        Qs[row][lc] = qv.x; Qs[row][lc+1] = qv.y; Qs[row][lc+2] = qv.z; Qs[row][lc+3] = qv.w;
        const float* kp = g_qkv + (size_t)(b*Tn + kt*64 + row) * (3*Dm) + Dm + h*HSz + lc;
        float4 kv = *(const float4*)kp;
        Ks[row][lc] = kv.x; Ks[row][lc+1] = kv.y; Ks[row][lc+2] = kv.z; Ks[row][lc+3] = kv.w;
    }
    __syncthreads();
    int tr = lr * 4, tc = lc;   // 4x4 microtile
    float acc[4][4] = {};
    #pragma unroll
    for (int kk = 0; kk < 64; kk++) {
        float a[4], bb[4];
        #pragma unroll
        for (int i = 0; i < 4; i++) a[i]  = Qs[tr + i][kk];
        #pragma unroll
        for (int j = 0; j < 4; j++) bb[j] = Ks[tc + j][kk];
        #pragma unroll
        for (int i = 0; i < 4; i++)
            #pragma unroll
            for (int j = 0; j < 4; j++) acc[i][j] += a[i] * bb[j];
    }
    float* outp = attn + (size_t)bh * Tn * Tn;
    #pragma unroll
    for (int i = 0; i < 4; i++)
        #pragma unroll
        for (int j = 0; j < 4; j++)
            outp[(size_t)(qt*64 + tr + i) * Tn + kt*64 + tc + j] = acc[i][j] * SCALE;
}

// ---------------- causal softmax in-place over d_out attn rows ------------
__global__ void __launch_bounds__(256) softmax_kernel(float* __restrict__ attn) {
    int t = blockIdx.x, bh = blockIdx.y, tid = threadIdx.x;
    float* row = attn + (size_t)bh * Tn * Tn + (size_t)t * Tn;
    int valid = t + 1;
    float v[4];
    float m = -1e30f;
    #pragma unroll
    for (int i = 0; i < 4; i++) {
        int j = tid + i*256;
        v[i] = row[j];
        if (j < valid) m = fmaxf(m, v[i]);
    }
    __shared__ float red[256];
    red[tid] = m; __syncthreads();
    for (int st = 128; st > 0; st >>= 1) { if (tid < st) red[tid] = fmaxf(red[tid], red[tid+st]); __syncthreads(); }
    m = red[0]; __syncthreads();
    float s = 0.f;
    #pragma unroll
    for (int i = 0; i < 4; i++) {
        int j = tid + i*256;
        float e = (j < valid) ? expf(v[i] - m) : 0.f;
        v[i] = e; s += e;
    }
    red[tid] = s; __syncthreads();
    for (int st = 128; st > 0; st >>= 1) { if (tid < st) red[tid] += red[tid+st]; __syncthreads(); }
    float inv = 1.0f / red[0];
    #pragma unroll
    for (int i = 0; i < 4; i++) row[tid + i*256] = v[i] * inv;
}

// ---------------- O = P @ V (causal k-loop) -------------------------------
// NOTE: attn base is d_out+1 (4 mod 16 bytes) -> scalar loads only.
__global__ void __launch_bounds__(256) av_kernel(const float* __restrict__ attn,
                                                 float* __restrict__ O) {
    int qt = blockIdx.x, bh = blockIdx.y;
    int b = bh >> 4, h = bh & 15;
    __shared__ float Ps[64][68];
    __shared__ float Vs[64][68];
    int tid = threadIdx.x;
    int lr = tid >> 4;
    int lc = (tid & 15) * 4;
    int tr = lr * 4, tc = lc;
    float acc[4][4] = {};
    const float* abase = attn + (size_t)bh * Tn * Tn;
    for (int kt = 0; kt <= qt; kt++) {
        #pragma unroll
        for (int r = 0; r < 4; r++) {
            int row = r * 16 + lr;
            const float* pp = abase + (size_t)(qt*64 + row) * Tn + kt*64 + lc;
            Ps[row][lc]   = pp[0];
            Ps[row][lc+1] = pp[1];
            Ps[row][lc+2] = pp[2];
            Ps[row][lc+3] = pp[3];
            const float* vp = g_qkv + (size_t)(b*Tn + kt*64 + row) * (3*Dm) + 2*Dm + h*HSz + lc;
            float4 vv = *(const float4*)vp;
            Vs[row][lc] = vv.x; Vs[row][lc+1] = vv.y; Vs[row][lc+2] = vv.z; Vs[row][lc+3] = vv.w;
        }
        __syncthreads();
        #pragma unroll
        for (int kk = 0; kk < 64; kk++) {
            float a[4], bb[4];
            #pragma unroll
            for (int i = 0; i < 4; i++) a[i]  = Ps[tr + i][kk];
            #pragma unroll
            for (int j = 0; j < 4; j++) bb[j] = Vs[kk][tc + j];
            #pragma unroll
            for (int i = 0; i < 4; i++)
                #pragma unroll
                for (int j = 0; j < 4; j++) acc[i][j] += a[i] * bb[j];
        }
        __syncthreads();
    }
    #pragma unroll
    for (int i = 0; i < 4; i++)
        #pragma unroll
        for (int j = 0; j < 4; j++)
            O[(size_t)(b*Tn + qt*64 + tr + i) * Dm + h*HSz + tc + j] = acc[i][j];
}

// ---------------- bf16 conversion helpers for the LM head -----------------
__global__ void h2b_kernel() {
    int gid = blockIdx.x * 256 + threadIdx.x;
    g_hb[gid] = __float2bfloat16(g_h[gid]);
}

// Wlm [D,V] row-major -> g_wlmb [V,D] bf16 (tiled transpose)
__global__ void wlm_trans_kernel(const float* __restrict__ W) {
    __shared__ float tile[32][33];
    int v0 = blockIdx.x * 32, d0 = blockIdx.y * 32;
    int tx = threadIdx.x, ty = threadIdx.y;   // 32 x 8
    #pragma unroll
    for (int i = 0; i < 32; i += 8)
        tile[ty + i][tx] = W[(size_t)(d0 + ty + i) * Vn + v0 + tx];
    __syncthreads();
    #pragma unroll
    for (int i = 0; i < 32; i += 8)
        g_wlmb[(size_t)(v0 + ty + i) * Dm + d0 + tx] = __float2bfloat16(tile[tx][ty + i]);
}

// ---------------- bf16 tensor-core LM head (mma.sync, compute_80+) --------
// C[4096,32000] = A[4096,1024](bf16) @ B^T (B = g_wlmb [32000,1024] bf16) + blm
// Tile 128x128, BK=32, 8 warps in 2(M)x4(N); warp tile 64x32 =
// 4x4 frags of m16n8k16. A .row via ldmatrix.x4, B .col via ldmatrix.x2.
__global__ void __launch_bounds__(256) lm_head_kernel(const float* __restrict__ blm,
                                                      float* __restrict__ Cout) {
    __shared__ __nv_bfloat16 Asm[128][40];   // 40-elem (80B) rows: conflict-free ldmatrix
    __shared__ __nv_bfloat16 Bsm[128][40];
    int tid = threadIdx.x;
    int warp = tid >> 5, lane = tid & 31;
    int warpM = warp >> 2, warpN = warp & 3;        // 2 x 4
    int mbase = blockIdx.y * 128, nbase = blockIdx.x * 128;

    float acc[4][4][4];
    #pragma unroll
    for (int mi = 0; mi < 4; mi++)
        #pragma unroll
        for (int ni = 0; ni < 4; ni++)
            #pragma unroll
            for (int r = 0; r < 4; r++) acc[mi][ni][r] = 0.f;

    const __nv_bfloat16* aG = g_hb   + (size_t)mbase * Dm;
    const __nv_bfloat16* bG = g_wlmb + (size_t)nbase * Dm;

    for (int k0 = 0; k0 < Dm; k0 += 32) {
        #pragma unroll
        for (int i = 0; i < 2; i++) {
            int unit = tid + i * 256;          // 0..511
            int row = unit >> 2;
            int ch  = (unit & 3) * 8;          // bf16 column offset
            *(uint4*)&Asm[row][ch] = *(const uint4*)(aG + (size_t)row * Dm + k0 + ch);
            *(uint4*)&Bsm[row][ch] = *(const uint4*)(bG + (size_t)row * Dm + k0 + ch);
        }
        __syncthreads();

        #pragma unroll
        for (int s = 0; s < 2; s++) {
            uint32_t a[4][4];
            #pragma unroll
            for (int mi = 0; mi < 4; mi++) {
                int row = warpM * 64 + mi * 16 + (lane & 15);
                int col = s * 16 + ((lane >> 4) << 3);
                uint32_t addr = (uint32_t)__cvta_generic_to_shared(&Asm[row][col]);
                asm volatile("ldmatrix.sync.aligned.m8n8.x4.shared.b16 {%0,%1,%2,%3}, [%4];"
                    : "=r"(a[mi][0]), "=r"(a[mi][1]), "=r"(a[mi][2]), "=r"(a[mi][3])
                    : "r"(addr));
            }
            uint32_t bf[4][2];
            #pragma unroll
            for (int ni = 0; ni < 4; ni++) {
                int row = warpN * 32 + ni * 8 + (lane & 7);
                int col = s * 16 + (((lane >> 3) & 1) << 3);
                uint32_t addr = (uint32_t)__cvta_generic_to_shared(&Bsm[row][col]);
                asm volatile("ldmatrix.sync.aligned.m8n8.x2.shared.b16 {%0,%1}, [%2];"
                    : "=r"(bf[ni][0]), "=r"(bf[ni][1]) : "r"(addr));
            }
            #pragma unroll
            for (int mi = 0; mi < 4; mi++)
                #pragma unroll
                for (int ni = 0; ni < 4; ni++)
                    asm volatile(
                        "mma.sync.aligned.m16n8k16.row.col.f32.bf16.bf16.f32 "
                        "{%0,%1,%2,%3}, {%4,%5,%6,%7}, {%8,%9}, {%0,%1,%2,%3};"
                        : "+f"(acc[mi][ni][0]), "+f"(acc[mi][ni][1]),
                          "+f"(acc[mi][ni][2]), "+f"(acc[mi][ni][3])
                        : "r"(a[mi][0]), "r"(a[mi][1]), "r"(a[mi][2]), "r"(a[mi][3]),
                          "r"(bf[ni][0]), "r"(bf[ni][1]));
        }
        __syncthreads();
    }

    int mrow = mbase + warpM * 64;
    int ncol = nbase + warpN * 32;
    #pragma unroll
    for (int mi = 0; mi < 4; mi++) {
        #pragma unroll
        for (int ni = 0; ni < 4; ni++) {
            int m0 = mrow + mi * 16 + (lane >> 2);
            int n0 = ncol + ni * 8 + 2 * (lane & 3);
            float2 bv = *(const float2*)(blm + n0);
            float2 o0 = { acc[mi][ni][0] + bv.x, acc[mi][ni][1] + bv.y };
            float2 o1 = { acc[mi][ni][2] + bv.x, acc[mi][ni][3] + bv.y };
            *(float2*)(Cout + (size_t)m0 * Vn + n0)       = o0;
            *(float2*)(Cout + (size_t)(m0 + 8) * Vn + n0) = o1;
        }
    }
}

// ---------------- per-row NLL over 32000-way logits -----------------------
__global__ void __launch_bounds__(512) nll_kernel(const int* __restrict__ targets) {
    int row = blockIdx.x, tid = threadIdx.x;
    const float* lr = g_logits + (size_t)row * Vn;
    float m = -1e30f;
    for (int j = tid; j < Vn; j += 512) m = fmaxf(m, lr[j]);
    __shared__ float red[512];
    red[tid] = m; __syncthreads();
    for (int st = 256; st > 0; st >>= 1) { if (tid < st) red[tid] = fmaxf(red[tid], red[tid+st]); __syncthreads(); }
    m = red[0]; __syncthreads();
    float s = 0.f;
    for (int j = tid; j < Vn; j += 512) s += expf(lr[j] - m);
    red[tid] = s; __syncthreads();
    for (int st = 256; st > 0; st >>= 1) { if (tid < st) red[tid] += red[tid+st]; __syncthreads(); }
    if (tid == 0) {
        int tg = targets[row];
        g_nll[row] = -(lr[tg] - m - logf(red[0]));
    }
}

__global__ void __launch_bounds__(256) loss_reduce_kernel(float* __restrict__ out) {
    int tid = threadIdx.x;
    float s = 0.f;
    for (int i = tid; i < BT; i += 256) s += g_nll[i];
    __shared__ float red[256];
    red[tid] = s; __syncthreads();
    for (int st = 128; st > 0; st >>= 1) { if (tid < st) red[tid] += red[tid+st]; __syncthreads(); }
    if (tid == 0) out[0] = red[0] / (float)BT;
}

// ---------------- launch ---------------------------------------------------
extern "C" void kernel_launch(void* const* d_in, const int* in_sizes, int n_in,
                              void* d_out, int out_size) {
    const int*   idx     = (const int*)  d_in[0];
    const int*   targets = (const int*)  d_in[1];
    const float* tok     = (const float*)d_in[2];
    const float* pos     = (const float*)d_in[3];
    const float* ln1_g   = (const float*)d_in[4];
    const float* ln1_b   = (const float*)d_in[5];
    const float* Wq      = (const float*)d_in[6];
    const float* Wk      = (const float*)d_in[7];
    const float* Wv      = (const float*)d_in[8];
    const float* Wp      = (const float*)d_in[9];
    const float* bp      = (const float*)d_in[10];
    const float* ln2_g   = (const float*)d_in[11];
    const float* ln2_b   = (const float*)d_in[12];
    const float* W1      = (const float*)d_in[13];
    const float* b1      = (const float*)d_in[14];
    const float* W2      = (const float*)d_in[15];
    const float* b2      = (const float*)d_in[16];
    const float* lnf_g   = (const float*)d_in[17];
    const float* lnf_b   = (const float*)d_in[18];
    const float* Wlm     = (const float*)d_in[19];
    const float* blm     = (const float*)d_in[20];

    float* out = (float*)d_out;
    float* attn_all = out + 1;   // (loss, attn) flattened

    float *px, *ph, *pqkv, *po, *pffn, *pwt, *plogits;
    cudaGetSymbolAddress((void**)&px,      g_x);
    cudaGetSymbolAddress((void**)&ph,      g_h);
    cudaGetSymbolAddress((void**)&pqkv,    g_qkv);
    cudaGetSymbolAddress((void**)&po,      g_o);
    cudaGetSymbolAddress((void**)&pffn,    g_ffn);
    cudaGetSymbolAddress((void**)&pwt,     g_wt);
    cudaGetSymbolAddress((void**)&plogits, g_logits);

    embed_kernel<<<(BT*Dm)/256, 256>>>(idx, tok, pos);

    for (int l = 0; l < Ln; l++) {
        float* attn_l = attn_all + (size_t)l * Bsz * Hn * Tn * Tn;
        size_t woff = (size_t)l * Hn * Dm * HSz;

        ln_kernel<<<BT, 256>>>(px, ln1_g + l*Dm, ln1_b + l*Dm, ph);
        wtrans_kernel<<<(Dm*Dm)/256, 256>>>(Wq + woff, Wk + woff, Wv + woff);
        sgemm_kernel<<<dim3(3*Dm/128, BT/128), 256>>>(ph, pwt, nullptr, pqkv,
                                                      BT, 3*Dm, Dm, 0);
        scores_kernel<<<dim3(Tn/64, Tn/64, Bsz*Hn), 256>>>(attn_l);
        softmax_kernel<<<dim3(Tn, Bsz*Hn), 256>>>(attn_l);
        av_kernel<<<dim3(Tn/64, Bsz*Hn), 256>>>(attn_l, po);
        sgemm_kernel<<<dim3(Dm/128, BT/128), 256>>>(po, Wp + (size_t)l*Dm*Dm,
                                                    bp + l*Dm, px,
                                                    BT, Dm, Dm, FLAG_RESID);
        ln_kernel<<<BT, 256>>>(px, ln2_g + l*Dm, ln2_b + l*Dm, ph);
        sgemm_kernel<<<dim3(FFn/128, BT/128), 256>>>(ph, W1 + (size_t)l*Dm*FFn,
                                                     b1 + l*FFn, pffn,
                                                     BT, FFn, Dm, FLAG_RELU);
        sgemm_kernel<<<dim3(Dm/128, BT/128), 256>>>(pffn, W2 + (size_t)l*FFn*Dm,
                                                    b2 + l*Dm, px,
                                                    BT, Dm, FFn, FLAG_RESID);
    }

    ln_kernel<<<BT, 256>>>(px, lnf_g, lnf_b, ph);
    h2b_kernel<<<(BT*Dm)/256, 256>>>();
    wlm_trans_kernel<<<dim3(Vn/32, Dm/32), dim3(32, 8)>>>(Wlm);
    lm_head_kernel<<<dim3(Vn/128, BT/128), 256>>>(blm, plogits);
    nll_kernel<<<BT, 512>>>(targets);
    loss_reduce_kernel<<<1, 256>>>(out);
}

// round 14
// speedup vs baseline: 2.2406x; 1.1355x over previous
#include <cuda_runtime.h>
#include <cuda_bf16.h>
#include <math.h>
#include <stdint.h>

// Problem constants
#define Bsz 4
#define Tn  1024
#define Dm  1024
#define Hn  16
#define HSz 64
#define Ln  4
#define FFn 4096
#define Vn  32000
#define EPSf 1e-5f
#define BT  (Bsz*Tn)   // 4096
#define SCALE 0.125f   // HS^-0.5

// ---------------- scratch (device globals; allocation is forbidden) -------
__device__ float g_x[BT*Dm];              // residual stream        16 MB
__device__ float g_h[BT*Dm];              // layernorm output       16 MB
__device__ float g_qkv[BT*3*Dm];          // fused QKV              48 MB
__device__ float g_o[BT*Dm];              // attention output       16 MB
__device__ float g_ffn[BT*FFn];           // FFN activation         64 MB
__device__ float g_wt[Dm*3*Dm];           // transposed QKV weights 12 MB
__device__ float g_logits[(size_t)BT*Vn]; // logits                524 MB
__device__ float g_nll[BT];
__device__ __nv_bfloat16 g_hb[BT*Dm];               // bf16 LN-f out   8 MB
__device__ __nv_bfloat16 g_wlmb[(size_t)Vn*Dm];     // Wlm^T bf16     64 MB

// ---------------- embedding ----------------------------------------------
__global__ void embed_kernel(const int* __restrict__ idx,
                             const float* __restrict__ tok,
                             const float* __restrict__ pos) {
    int gid = blockIdx.x * 256 + threadIdx.x;      // BT*Dm threads
    int bt = gid >> 10;
    int d  = gid & 1023;
    int t  = bt & (Tn - 1);
    g_x[gid] = tok[(size_t)idx[bt] * Dm + d] + pos[t * Dm + d];
}

// ---------------- layernorm (row = 1024, block = 256) ---------------------
__global__ void ln_kernel(const float* __restrict__ x,
                          const float* __restrict__ g,
                          const float* __restrict__ b,
                          float* __restrict__ out) {
    int row = blockIdx.x, tid = threadIdx.x;
    const float* xr = x + (size_t)row * Dm;
    float v[4]; float s = 0.f;
    #pragma unroll
    for (int i = 0; i < 4; i++) { v[i] = xr[tid + i*256]; s += v[i]; }
    __shared__ float red[256];
    red[tid] = s; __syncthreads();
    for (int st = 128; st > 0; st >>= 1) { if (tid < st) red[tid] += red[tid+st]; __syncthreads(); }
    float m = red[0] * (1.0f / Dm);
    __syncthreads();
    float sq = 0.f;
    #pragma unroll
    for (int i = 0; i < 4; i++) { float d = v[i] - m; sq += d * d; }
    red[tid] = sq; __syncthreads();
    for (int st = 128; st > 0; st >>= 1) { if (tid < st) red[tid] += red[tid+st]; __syncthreads(); }
    float inv = rsqrtf(red[0] * (1.0f / Dm) + EPSf);
    #pragma unroll
    for (int i = 0; i < 4; i++) {
        int d = tid + i*256;
        out[(size_t)row * Dm + d] = (v[i] - m) * inv * g[d] + b[d];
    }
}

// ---------------- QKV weight transpose: [H,D,HS] -> [D, 3*D] --------------
__global__ void wtrans_kernel(const float* __restrict__ Wq,
                              const float* __restrict__ Wk,
                              const float* __restrict__ Wv) {
    int gid = blockIdx.x * 256 + threadIdx.x;   // Dm*Dm threads
    int d = gid >> 10;
    int c = gid & 1023;        // c = h*HS + s
    int h = c >> 6, s = c & 63;
    int src = (h * Dm + d) * HSz + s;
    g_wt[(size_t)d * 3*Dm + c]          = Wq[src];
    g_wt[(size_t)d * 3*Dm + Dm + c]     = Wk[src];
    g_wt[(size_t)d * 3*Dm + 2*Dm + c]   = Wv[src];
}

// ---------------- bf16x3 split tensor-core GEMM ---------------------------
// C[M,N] = A[M,K](fp32) @ B[K,N](fp32) (+bias)(+C)(relu), via bf16 hi/lo
// split: C = Ah*Bh + Ah*Bl + Al*Bh (error ~2^-18). Tile 128x128, BK=32,
// 256 threads = 8 warps (2M x 4N), warp tile 64x32, m16n8k16 frags.
#define FLAG_RELU  1
#define FLAG_RESID 2
__global__ void __launch_bounds__(256) gemm_x3_kernel(
        const float* __restrict__ A, const float* __restrict__ B,
        const float* __restrict__ bias, float* __restrict__ C,
        int M, int N, int K, int flags) {
    __shared__ __nv_bfloat16 Ahi[128][40], Alo[128][40];   // [m][k]
    __shared__ __nv_bfloat16 Bhi[128][40], Blo[128][40];   // [n][k] (transposed)
    int tid = threadIdx.x;
    int warp = tid >> 5, lane = tid & 31;
    int warpM = warp >> 2, warpN = warp & 3;
    int mbase = blockIdx.y * 128, nbase = blockIdx.x * 128;

    float acc[4][4][4];
    #pragma unroll
    for (int mi = 0; mi < 4; mi++)
        #pragma unroll
        for (int ni = 0; ni < 4; ni++)
            #pragma unroll
            for (int r = 0; r < 4; r++) acc[mi][ni][r] = 0.f;

    for (int k0 = 0; k0 < K; k0 += 32) {
        #pragma unroll
        for (int i = 0; i < 4; i++) {
            int unit = tid + i * 256;            // 0..1023
            // A: 128 rows x 32 cols (float4 per unit)
            {
                int row = unit >> 3, c4 = (unit & 7) * 4;
                float4 v = *(const float4*)(A + (size_t)(mbase + row) * K + k0 + c4);
                __nv_bfloat16 h0 = __float2bfloat16(v.x);
                __nv_bfloat16 h1 = __float2bfloat16(v.y);
                __nv_bfloat16 h2 = __float2bfloat16(v.z);
                __nv_bfloat16 h3 = __float2bfloat16(v.w);
                Ahi[row][c4+0] = h0; Alo[row][c4+0] = __float2bfloat16(v.x - __bfloat162float(h0));
                Ahi[row][c4+1] = h1; Alo[row][c4+1] = __float2bfloat16(v.y - __bfloat162float(h1));
                Ahi[row][c4+2] = h2; Alo[row][c4+2] = __float2bfloat16(v.z - __bfloat162float(h2));
                Ahi[row][c4+3] = h3; Alo[row][c4+3] = __float2bfloat16(v.w - __bfloat162float(h3));
            }
            // B: 32 k-rows x 128 n-cols, store transposed [n][k]
            {
                int kr = unit >> 5, c4 = (unit & 31) * 4;
                float4 v = *(const float4*)(B + (size_t)(k0 + kr) * N + nbase + c4);
                __nv_bfloat16 h0 = __float2bfloat16(v.x);
                __nv_bfloat16 h1 = __float2bfloat16(v.y);
                __nv_bfloat16 h2 = __float2bfloat16(v.z);
                __nv_bfloat16 h3 = __float2bfloat16(v.w);
                Bhi[c4+0][kr] = h0; Blo[c4+0][kr] = __float2bfloat16(v.x - __bfloat162float(h0));
                Bhi[c4+1][kr] = h1; Blo[c4+1][kr] = __float2bfloat16(v.y - __bfloat162float(h1));
                Bhi[c4+2][kr] = h2; Blo[c4+2][kr] = __float2bfloat16(v.z - __bfloat162float(h2));
                Bhi[c4+3][kr] = h3; Blo[c4+3][kr] = __float2bfloat16(v.w - __bfloat162float(h3));
            }
        }
        __syncthreads();

        #pragma unroll
        for (int s = 0; s < 2; s++) {
            int arow = warpM * 64 + (lane & 15);
            int acol = s * 16 + ((lane >> 4) << 3);
            int brow = warpN * 32 + (lane & 7);
            int bcol = s * 16 + (((lane >> 3) & 1) << 3);

            uint32_t ah[4][4];
            #pragma unroll
            for (int mi = 0; mi < 4; mi++) {
                uint32_t addr = (uint32_t)__cvta_generic_to_shared(&Ahi[arow + mi*16][acol]);
                asm volatile("ldmatrix.sync.aligned.m8n8.x4.shared.b16 {%0,%1,%2,%3}, [%4];"
                    : "=r"(ah[mi][0]), "=r"(ah[mi][1]), "=r"(ah[mi][2]), "=r"(ah[mi][3])
                    : "r"(addr));
            }
            uint32_t bh[4][2];
            #pragma unroll
            for (int ni = 0; ni < 4; ni++) {
                uint32_t addr = (uint32_t)__cvta_generic_to_shared(&Bhi[brow + ni*8][bcol]);
                asm volatile("ldmatrix.sync.aligned.m8n8.x2.shared.b16 {%0,%1}, [%2];"
                    : "=r"(bh[ni][0]), "=r"(bh[ni][1]) : "r"(addr));
            }
            // hi * hi
            #pragma unroll
            for (int mi = 0; mi < 4; mi++)
                #pragma unroll
                for (int ni = 0; ni < 4; ni++)
                    asm volatile(
                        "mma.sync.aligned.m16n8k16.row.col.f32.bf16.bf16.f32 "
                        "{%0,%1,%2,%3}, {%4,%5,%6,%7}, {%8,%9}, {%0,%1,%2,%3};"
                        : "+f"(acc[mi][ni][0]), "+f"(acc[mi][ni][1]),
                          "+f"(acc[mi][ni][2]), "+f"(acc[mi][ni][3])
                        : "r"(ah[mi][0]), "r"(ah[mi][1]), "r"(ah[mi][2]), "r"(ah[mi][3]),
                          "r"(bh[ni][0]), "r"(bh[ni][1]));
            // hi * lo
            uint32_t bl[4][2];
            #pragma unroll
            for (int ni = 0; ni < 4; ni++) {
                uint32_t addr = (uint32_t)__cvta_generic_to_shared(&Blo[brow + ni*8][bcol]);
                asm volatile("ldmatrix.sync.aligned.m8n8.x2.shared.b16 {%0,%1}, [%2];"
                    : "=r"(bl[ni][0]), "=r"(bl[ni][1]) : "r"(addr));
            }
            #pragma unroll
            for (int mi = 0; mi < 4; mi++)
                #pragma unroll
                for (int ni = 0; ni < 4; ni++)
                    asm volatile(
                        "mma.sync.aligned.m16n8k16.row.col.f32.bf16.bf16.f32 "
                        "{%0,%1,%2,%3}, {%4,%5,%6,%7}, {%8,%9}, {%0,%1,%2,%3};"
                        : "+f"(acc[mi][ni][0]), "+f"(acc[mi][ni][1]),
                          "+f"(acc[mi][ni][2]), "+f"(acc[mi][ni][3])
                        : "r"(ah[mi][0]), "r"(ah[mi][1]), "r"(ah[mi][2]), "r"(ah[mi][3]),
                          "r"(bl[ni][0]), "r"(bl[ni][1]));
            // lo * hi
            uint32_t al[4][4];
            #pragma unroll
            for (int mi = 0; mi < 4; mi++) {
                uint32_t addr = (uint32_t)__cvta_generic_to_shared(&Alo[arow + mi*16][acol]);
                asm volatile("ldmatrix.sync.aligned.m8n8.x4.shared.b16 {%0,%1,%2,%3}, [%4];"
                    : "=r"(al[mi][0]), "=r"(al[mi][1]), "=r"(al[mi][2]), "=r"(al[mi][3])
                    : "r"(addr));
            }
            #pragma unroll
            for (int mi = 0; mi < 4; mi++)
                #pragma unroll
                for (int ni = 0; ni < 4; ni++)
                    asm volatile(
                        "mma.sync.aligned.m16n8k16.row.col.f32.bf16.bf16.f32 "
                        "{%0,%1,%2,%3}, {%4,%5,%6,%7}, {%8,%9}, {%0,%1,%2,%3};"
                        : "+f"(acc[mi][ni][0]), "+f"(acc[mi][ni][1]),
                          "+f"(acc[mi][ni][2]), "+f"(acc[mi][ni][3])
                        : "r"(al[mi][0]), "r"(al[mi][1]), "r"(al[mi][2]), "r"(al[mi][3]),
                          "r"(bh[ni][0]), "r"(bh[ni][1]));
        }
        __syncthreads();
    }

    int mrow = mbase + warpM * 64;
    int ncol = nbase + warpN * 32;
    #pragma unroll
    for (int mi = 0; mi < 4; mi++) {
        #pragma unroll
        for (int ni = 0; ni < 4; ni++) {
            int m0 = mrow + mi * 16 + (lane >> 2);
            int n0 = ncol + ni * 8 + 2 * (lane & 3);
            float bx = 0.f, by = 0.f;
            if (bias) { float2 bv = *(const float2*)(bias + n0); bx = bv.x; by = bv.y; }
            float o00 = acc[mi][ni][0] + bx, o01 = acc[mi][ni][1] + by;
            float o10 = acc[mi][ni][2] + bx, o11 = acc[mi][ni][3] + by;
            float* q0 = C + (size_t)m0 * N + n0;
            float* q1 = C + (size_t)(m0 + 8) * N + n0;
            if (flags & FLAG_RESID) {
                float2 r0 = *(const float2*)q0;
                float2 r1 = *(const float2*)q1;
                o00 += r0.x; o01 += r0.y; o10 += r1.x; o11 += r1.y;
            }
            if (flags & FLAG_RELU) {
                o00 = fmaxf(o00, 0.f); o01 = fmaxf(o01, 0.f);
                o10 = fmaxf(o10, 0.f); o11 = fmaxf(o11, 0.f);
            }
            *(float2*)q0 = make_float2(o00, o01);
            *(float2*)q1 = make_float2(o10, o11);
        }
    }
}

// ---------------- attention scores: S = Q @ K^T * scale -------------------
__global__ void __launch_bounds__(256) scores_kernel(float* __restrict__ attn) {
    int kt = blockIdx.x, qt = blockIdx.y;
    if (kt > qt) return;
    int bh = blockIdx.z;
    int b = bh >> 4, h = bh & 15;
    __shared__ float Qs[64][68];
    __shared__ float Ks[64][68];
    int tid = threadIdx.x;
    int lr = tid >> 4;           // 0..15
    int lc = (tid & 15) * 4;     // 0..60
    #pragma unroll
    for (int r = 0; r < 4; r++) {
        int row = r * 16 + lr;
        const float* qp = g_qkv + (size_t)(b*Tn + qt*64 + row) * (3*Dm) + h*HSz + lc;
        float4 qv = *(const float4*)qp;
        Qs[row][lc] = qv.x; Qs[row][lc+1] = qv.y; Qs[row][lc+2] = qv.z; Qs[row][lc+3] = qv.w;
        const float* kp = g_qkv + (size_t)(b*Tn + kt*64 + row) * (3*Dm) + Dm + h*HSz + lc;
        float4 kv = *(const float4*)kp;
        Ks[row][lc] = kv.x; Ks[row][lc+1] = kv.y; Ks[row][lc+2] = kv.z; Ks[row][lc+3] = kv.w;
    }
    __syncthreads();
    int tr = lr * 4, tc = lc;   // 4x4 microtile
    float acc[4][4] = {};
    #pragma unroll
    for (int kk = 0; kk < 64; kk++) {
        float a[4], bb[4];
        #pragma unroll
        for (int i = 0; i < 4; i++) a[i]  = Qs[tr + i][kk];
        #pragma unroll
        for (int j = 0; j < 4; j++) bb[j] = Ks[tc + j][kk];
        #pragma unroll
        for (int i = 0; i < 4; i++)
            #pragma unroll
            for (int j = 0; j < 4; j++) acc[i][j] += a[i] * bb[j];
    }
    float* outp = attn + (size_t)bh * Tn * Tn;
    #pragma unroll
    for (int i = 0; i < 4; i++)
        #pragma unroll
        for (int j = 0; j < 4; j++)
            outp[(size_t)(qt*64 + tr + i) * Tn + kt*64 + tc + j] = acc[i][j] * SCALE;
}

// ---------------- causal softmax in-place over d_out attn rows ------------
__global__ void __launch_bounds__(256) softmax_kernel(float* __restrict__ attn) {
    int t = blockIdx.x, bh = blockIdx.y, tid = threadIdx.x;
    float* row = attn + (size_t)bh * Tn * Tn + (size_t)t * Tn;
    int valid = t + 1;
    float v[4];
    float m = -1e30f;
    #pragma unroll
    for (int i = 0; i < 4; i++) {
        int j = tid + i*256;
        v[i] = row[j];
        if (j < valid) m = fmaxf(m, v[i]);
    }
    __shared__ float red[256];
    red[tid] = m; __syncthreads();
    for (int st = 128; st > 0; st >>= 1) { if (tid < st) red[tid] = fmaxf(red[tid], red[tid+st]); __syncthreads(); }
    m = red[0]; __syncthreads();
    float s = 0.f;
    #pragma unroll
    for (int i = 0; i < 4; i++) {
        int j = tid + i*256;
        float e = (j < valid) ? expf(v[i] - m) : 0.f;
        v[i] = e; s += e;
    }
    red[tid] = s; __syncthreads();
    for (int st = 128; st > 0; st >>= 1) { if (tid < st) red[tid] += red[tid+st]; __syncthreads(); }
    float inv = 1.0f / red[0];
    #pragma unroll
    for (int i = 0; i < 4; i++) row[tid + i*256] = v[i] * inv;
}

// ---------------- O = P @ V (causal k-loop) -------------------------------
// NOTE: attn base is d_out+1 (4 mod 16 bytes) -> scalar loads only.
__global__ void __launch_bounds__(256) av_kernel(const float* __restrict__ attn,
                                                 float* __restrict__ O) {
    int qt = blockIdx.x, bh = blockIdx.y;
    int b = bh >> 4, h = bh & 15;
    __shared__ float Ps[64][68];
    __shared__ float Vs[64][68];
    int tid = threadIdx.x;
    int lr = tid >> 4;
    int lc = (tid & 15) * 4;
    int tr = lr * 4, tc = lc;
    float acc[4][4] = {};
    const float* abase = attn + (size_t)bh * Tn * Tn;
    for (int kt = 0; kt <= qt; kt++) {
        #pragma unroll
        for (int r = 0; r < 4; r++) {
            int row = r * 16 + lr;
            const float* pp = abase + (size_t)(qt*64 + row) * Tn + kt*64 + lc;
            Ps[row][lc]   = pp[0];
            Ps[row][lc+1] = pp[1];
            Ps[row][lc+2] = pp[2];
            Ps[row][lc+3] = pp[3];
            const float* vp = g_qkv + (size_t)(b*Tn + kt*64 + row) * (3*Dm) + 2*Dm + h*HSz + lc;
            float4 vv = *(const float4*)vp;
            Vs[row][lc] = vv.x; Vs[row][lc+1] = vv.y; Vs[row][lc+2] = vv.z; Vs[row][lc+3] = vv.w;
        }
        __syncthreads();
        #pragma unroll
        for (int kk = 0; kk < 64; kk++) {
            float a[4], bb[4];
            #pragma unroll
            for (int i = 0; i < 4; i++) a[i]  = Ps[tr + i][kk];
            #pragma unroll
            for (int j = 0; j < 4; j++) bb[j] = Vs[kk][tc + j];
            #pragma unroll
            for (int i = 0; i < 4; i++)
                #pragma unroll
                for (int j = 0; j < 4; j++) acc[i][j] += a[i] * bb[j];
        }
        __syncthreads();
    }
    #pragma unroll
    for (int i = 0; i < 4; i++)
        #pragma unroll
        for (int j = 0; j < 4; j++)
            O[(size_t)(b*Tn + qt*64 + tr + i) * Dm + h*HSz + tc + j] = acc[i][j];
}

// ---------------- bf16 conversion helpers for the LM head -----------------
__global__ void h2b_kernel() {
    int gid = blockIdx.x * 256 + threadIdx.x;
    g_hb[gid] = __float2bfloat16(g_h[gid]);
}

// Wlm [D,V] row-major -> g_wlmb [V,D] bf16 (tiled transpose)
__global__ void wlm_trans_kernel(const float* __restrict__ W) {
    __shared__ float tile[32][33];
    int v0 = blockIdx.x * 32, d0 = blockIdx.y * 32;
    int tx = threadIdx.x, ty = threadIdx.y;   // 32 x 8
    #pragma unroll
    for (int i = 0; i < 32; i += 8)
        tile[ty + i][tx] = W[(size_t)(d0 + ty + i) * Vn + v0 + tx];
    __syncthreads();
    #pragma unroll
    for (int i = 0; i < 32; i += 8)
        g_wlmb[(size_t)(v0 + ty + i) * Dm + d0 + tx] = __float2bfloat16(tile[tx][ty + i]);
}

// ---------------- bf16 tensor-core LM head (mma.sync) ---------------------
__global__ void __launch_bounds__(256) lm_head_kernel(const float* __restrict__ blm,
                                                      float* __restrict__ Cout) {
    __shared__ __nv_bfloat16 Asm[128][40];
    __shared__ __nv_bfloat16 Bsm[128][40];
    int tid = threadIdx.x;
    int warp = tid >> 5, lane = tid & 31;
    int warpM = warp >> 2, warpN = warp & 3;        // 2 x 4
    int mbase = blockIdx.y * 128, nbase = blockIdx.x * 128;

    float acc[4][4][4];
    #pragma unroll
    for (int mi = 0; mi < 4; mi++)
        #pragma unroll
        for (int ni = 0; ni < 4; ni++)
            #pragma unroll
            for (int r = 0; r < 4; r++) acc[mi][ni][r] = 0.f;

    const __nv_bfloat16* aG = g_hb   + (size_t)mbase * Dm;
    const __nv_bfloat16* bG = g_wlmb + (size_t)nbase * Dm;

    for (int k0 = 0; k0 < Dm; k0 += 32) {
        #pragma unroll
        for (int i = 0; i < 2; i++) {
            int unit = tid + i * 256;          // 0..511
            int row = unit >> 2;
            int ch  = (unit & 3) * 8;          // bf16 column offset
            *(uint4*)&Asm[row][ch] = *(const uint4*)(aG + (size_t)row * Dm + k0 + ch);
            *(uint4*)&Bsm[row][ch] = *(const uint4*)(bG + (size_t)row * Dm + k0 + ch);
        }
        __syncthreads();

        #pragma unroll
        for (int s = 0; s < 2; s++) {
            uint32_t a[4][4];
            #pragma unroll
            for (int mi = 0; mi < 4; mi++) {
                int row = warpM * 64 + mi * 16 + (lane & 15);
                int col = s * 16 + ((lane >> 4) << 3);
                uint32_t addr = (uint32_t)__cvta_generic_to_shared(&Asm[row][col]);
                asm volatile("ldmatrix.sync.aligned.m8n8.x4.shared.b16 {%0,%1,%2,%3}, [%4];"
                    : "=r"(a[mi][0]), "=r"(a[mi][1]), "=r"(a[mi][2]), "=r"(a[mi][3])
                    : "r"(addr));
            }
            uint32_t bf[4][2];
            #pragma unroll
            for (int ni = 0; ni < 4; ni++) {
                int row = warpN * 32 + ni * 8 + (lane & 7);
                int col = s * 16 + (((lane >> 3) & 1) << 3);
                uint32_t addr = (uint32_t)__cvta_generic_to_shared(&Bsm[row][col]);
                asm volatile("ldmatrix.sync.aligned.m8n8.x2.shared.b16 {%0,%1}, [%2];"
                    : "=r"(bf[ni][0]), "=r"(bf[ni][1]) : "r"(addr));
            }
            #pragma unroll
            for (int mi = 0; mi < 4; mi++)
                #pragma unroll
                for (int ni = 0; ni < 4; ni++)
                    asm volatile(
                        "mma.sync.aligned.m16n8k16.row.col.f32.bf16.bf16.f32 "
                        "{%0,%1,%2,%3}, {%4,%5,%6,%7}, {%8,%9}, {%0,%1,%2,%3};"
                        : "+f"(acc[mi][ni][0]), "+f"(acc[mi][ni][1]),
                          "+f"(acc[mi][ni][2]), "+f"(acc[mi][ni][3])
                        : "r"(a[mi][0]), "r"(a[mi][1]), "r"(a[mi][2]), "r"(a[mi][3]),
                          "r"(bf[ni][0]), "r"(bf[ni][1]));
        }
        __syncthreads();
    }

    int mrow = mbase + warpM * 64;
    int ncol = nbase + warpN * 32;
    #pragma unroll
    for (int mi = 0; mi < 4; mi++) {
        #pragma unroll
        for (int ni = 0; ni < 4; ni++) {
            int m0 = mrow + mi * 16 + (lane >> 2);
            int n0 = ncol + ni * 8 + 2 * (lane & 3);
            float2 bv = *(const float2*)(blm + n0);
            float2 o0 = { acc[mi][ni][0] + bv.x, acc[mi][ni][1] + bv.y };
            float2 o1 = { acc[mi][ni][2] + bv.x, acc[mi][ni][3] + bv.y };
            *(float2*)(Cout + (size_t)m0 * Vn + n0)       = o0;
            *(float2*)(Cout + (size_t)(m0 + 8) * Vn + n0) = o1;
        }
    }
}

// ---------------- per-row NLL over 32000-way logits -----------------------
__global__ void __launch_bounds__(512) nll_kernel(const int* __restrict__ targets) {
    int row = blockIdx.x, tid = threadIdx.x;
    const float* lr = g_logits + (size_t)row * Vn;
    float m = -1e30f;
    for (int j = tid; j < Vn; j += 512) m = fmaxf(m, lr[j]);
    __shared__ float red[512];
    red[tid] = m; __syncthreads();
    for (int st = 256; st > 0; st >>= 1) { if (tid < st) red[tid] = fmaxf(red[tid], red[tid+st]); __syncthreads(); }
    m = red[0]; __syncthreads();
    float s = 0.f;
    for (int j = tid; j < Vn; j += 512) s += expf(lr[j] - m);
    red[tid] = s; __syncthreads();
    for (int st = 256; st > 0; st >>= 1) { if (tid < st) red[tid] += red[tid+st]; __syncthreads(); }
    if (tid == 0) {
        int tg = targets[row];
        g_nll[row] = -(lr[tg] - m - logf(red[0]));
    }
}

__global__ void __launch_bounds__(256) loss_reduce_kernel(float* __restrict__ out) {
    int tid = threadIdx.x;
    float s = 0.f;
    for (int i = tid; i < BT; i += 256) s += g_nll[i];
    __shared__ float red[256];
    red[tid] = s; __syncthreads();
    for (int st = 128; st > 0; st >>= 1) { if (tid < st) red[tid] += red[tid+st]; __syncthreads(); }
    if (tid == 0) out[0] = red[0] / (float)BT;
}

// ---------------- launch ---------------------------------------------------
extern "C" void kernel_launch(void* const* d_in, const int* in_sizes, int n_in,
                              void* d_out, int out_size) {
    const int*   idx     = (const int*)  d_in[0];
    const int*   targets = (const int*)  d_in[1];
    const float* tok     = (const float*)d_in[2];
    const float* pos     = (const float*)d_in[3];
    const float* ln1_g   = (const float*)d_in[4];
    const float* ln1_b   = (const float*)d_in[5];
    const float* Wq      = (const float*)d_in[6];
    const float* Wk      = (const float*)d_in[7];
    const float* Wv      = (const float*)d_in[8];
    const float* Wp      = (const float*)d_in[9];
    const float* bp      = (const float*)d_in[10];
    const float* ln2_g   = (const float*)d_in[11];
    const float* ln2_b   = (const float*)d_in[12];
    const float* W1      = (const float*)d_in[13];
    const float* b1      = (const float*)d_in[14];
    const float* W2      = (const float*)d_in[15];
    const float* b2      = (const float*)d_in[16];
    const float* lnf_g   = (const float*)d_in[17];
    const float* lnf_b   = (const float*)d_in[18];
    const float* Wlm     = (const float*)d_in[19];
    const float* blm     = (const float*)d_in[20];

    float* out = (float*)d_out;
    float* attn_all = out + 1;   // (loss, attn) flattened

    float *px, *ph, *pqkv, *po, *pffn, *pwt, *plogits;
    cudaGetSymbolAddress((void**)&px,      g_x);
    cudaGetSymbolAddress((void**)&ph,      g_h);
    cudaGetSymbolAddress((void**)&pqkv,    g_qkv);
    cudaGetSymbolAddress((void**)&po,      g_o);
    cudaGetSymbolAddress((void**)&pffn,    g_ffn);
    cudaGetSymbolAddress((void**)&pwt,     g_wt);
    cudaGetSymbolAddress((void**)&plogits, g_logits);

    embed_kernel<<<(BT*Dm)/256, 256>>>(idx, tok, pos);

    for (int l = 0; l < Ln; l++) {
        float* attn_l = attn_all + (size_t)l * Bsz * Hn * Tn * Tn;
        size_t woff = (size_t)l * Hn * Dm * HSz;

        ln_kernel<<<BT, 256>>>(px, ln1_g + l*Dm, ln1_b + l*Dm, ph);
        wtrans_kernel<<<(Dm*Dm)/256, 256>>>(Wq + woff, Wk + woff, Wv + woff);
        gemm_x3_kernel<<<dim3(3*Dm/128, BT/128), 256>>>(ph, pwt, nullptr, pqkv,
                                                        BT, 3*Dm, Dm, 0);
        scores_kernel<<<dim3(Tn/64, Tn/64, Bsz*Hn), 256>>>(attn_l);
        softmax_kernel<<<dim3(Tn, Bsz*Hn), 256>>>(attn_l);
        av_kernel<<<dim3(Tn/64, Bsz*Hn), 256>>>(attn_l, po);
        gemm_x3_kernel<<<dim3(Dm/128, BT/128), 256>>>(po, Wp + (size_t)l*Dm*Dm,
                                                      bp + l*Dm, px,
                                                      BT, Dm, Dm, FLAG_RESID);
        ln_kernel<<<BT, 256>>>(px, ln2_g + l*Dm, ln2_b + l*Dm, ph);
        gemm_x3_kernel<<<dim3(FFn/128, BT/128), 256>>>(ph, W1 + (size_t)l*Dm*FFn,
                                                       b1 + l*FFn, pffn,
                                                       BT, FFn, Dm, FLAG_RELU);
        gemm_x3_kernel<<<dim3(Dm/128, BT/128), 256>>>(pffn, W2 + (size_t)l*FFn*Dm,
                                                      b2 + l*Dm, px,
                                                      BT, Dm, FFn, FLAG_RESID);
    }

    ln_kernel<<<BT, 256>>>(px, lnf_g, lnf_b, ph);
    h2b_kernel<<<(BT*Dm)/256, 256>>>();
    wlm_trans_kernel<<<dim3(Vn/32, Dm/32), dim3(32, 8)>>>(Wlm);
    lm_head_kernel<<<dim3(Vn/128, BT/128), 256>>>(blm, plogits);
    nll_kernel<<<BT, 512>>>(targets);
    loss_reduce_kernel<<<1, 256>>>(out);
}

// round 15
// speedup vs baseline: 3.9149x; 1.7473x over previous
#include <cuda_runtime.h>
#include <cuda_bf16.h>
#include <math.h>
#include <stdint.h>

// Problem constants
#define Bsz 4
#define Tn  1024
#define Dm  1024
#define Hn  16
#define HSz 64
#define Ln  4
#define FFn 4096
#define Vn  32000
#define EPSf 1e-5f
#define BT  (Bsz*Tn)   // 4096
#define SCALE 0.125f   // HS^-0.5

// ---------------- scratch (device globals; allocation is forbidden) -------
__device__ float g_x[BT*Dm];              // residual stream        16 MB
__device__ float g_h[BT*Dm];              // layernorm output       16 MB
__device__ float g_qkv[BT*3*Dm];          // fused QKV              48 MB
__device__ float g_o[BT*Dm];              // attention output       16 MB
__device__ float g_ffn[BT*FFn];           // FFN activation         64 MB
__device__ float g_wt[Dm*3*Dm];           // transposed QKV weights 12 MB
__device__ float g_logits[(size_t)BT*Vn]; // logits                524 MB
__device__ float g_nll[BT];
__device__ __nv_bfloat16 g_hb[BT*Dm];               // bf16 LN-f out   8 MB
__device__ __nv_bfloat16 g_wlmb[(size_t)Vn*Dm];     // Wlm^T bf16     64 MB

__device__ __forceinline__ uint32_t pack_bf2(__nv_bfloat16 a, __nv_bfloat16 b) {
    __nv_bfloat162 t = __halves2bfloat162(a, b);
    return *reinterpret_cast<uint32_t*>(&t);
}

// ---------------- embedding ----------------------------------------------
__global__ void embed_kernel(const int* __restrict__ idx,
                             const float* __restrict__ tok,
                             const float* __restrict__ pos) {
    int gid = blockIdx.x * 256 + threadIdx.x;      // BT*Dm threads
    int bt = gid >> 10;
    int d  = gid & 1023;
    int t  = bt & (Tn - 1);
    g_x[gid] = tok[(size_t)idx[bt] * Dm + d] + pos[t * Dm + d];
}

// ---------------- layernorm (row = 1024, block = 256) ---------------------
__global__ void ln_kernel(const float* __restrict__ x,
                          const float* __restrict__ g,
                          const float* __restrict__ b,
                          float* __restrict__ out) {
    int row = blockIdx.x, tid = threadIdx.x;
    const float* xr = x + (size_t)row * Dm;
    float v[4]; float s = 0.f;
    #pragma unroll
    for (int i = 0; i < 4; i++) { v[i] = xr[tid + i*256]; s += v[i]; }
    __shared__ float red[256];
    red[tid] = s; __syncthreads();
    for (int st = 128; st > 0; st >>= 1) { if (tid < st) red[tid] += red[tid+st]; __syncthreads(); }
    float m = red[0] * (1.0f / Dm);
    __syncthreads();
    float sq = 0.f;
    #pragma unroll
    for (int i = 0; i < 4; i++) { float d = v[i] - m; sq += d * d; }
    red[tid] = sq; __syncthreads();
    for (int st = 128; st > 0; st >>= 1) { if (tid < st) red[tid] += red[tid+st]; __syncthreads(); }
    float inv = rsqrtf(red[0] * (1.0f / Dm) + EPSf);
    #pragma unroll
    for (int i = 0; i < 4; i++) {
        int d = tid + i*256;
        out[(size_t)row * Dm + d] = (v[i] - m) * inv * g[d] + b[d];
    }
}

// ---------------- QKV weight transpose: [H,D,HS] -> [D, 3*D] --------------
__global__ void wtrans_kernel(const float* __restrict__ Wq,
                              const float* __restrict__ Wk,
                              const float* __restrict__ Wv) {
    int gid = blockIdx.x * 256 + threadIdx.x;   // Dm*Dm threads
    int d = gid >> 10;
    int c = gid & 1023;        // c = h*HS + s
    int h = c >> 6, s = c & 63;
    int src = (h * Dm + d) * HSz + s;
    g_wt[(size_t)d * 3*Dm + c]          = Wq[src];
    g_wt[(size_t)d * 3*Dm + Dm + c]     = Wk[src];
    g_wt[(size_t)d * 3*Dm + 2*Dm + c]   = Wv[src];
}

// ---------------- bf16x3 split tensor-core GEMM (v2) ----------------------
// C[M,N] = A[M,K](fp32) @ B[K,N](fp32) (+bias)(+C)(relu), via bf16 hi/lo
// split: C = Ah*Bh + Ah*Bl + Al*Bh (error ~2^-18). Tile 128x128, BK=32.
// A smem [m][k] (pad 40); B smem [k][n] (pad 136) read via ldmatrix.trans.
// All conversion stores are vectorized 8-byte STS.
#define FLAG_RELU  1
#define FLAG_RESID 2
__global__ void __launch_bounds__(256) gemm_x3_kernel(
        const float* __restrict__ A, const float* __restrict__ B,
        const float* __restrict__ bias, float* __restrict__ C,
        int M, int N, int K, int flags) {
    __shared__ __nv_bfloat16 Ahi[128][40], Alo[128][40];   // [m][k]
    __shared__ __nv_bfloat16 Bhi[32][136], Blo[32][136];   // [k][n]
    int tid = threadIdx.x;
    int warp = tid >> 5, lane = tid & 31;
    int warpM = warp >> 2, warpN = warp & 3;
    int mbase = blockIdx.y * 128, nbase = blockIdx.x * 128;

    float acc[4][4][4];
    #pragma unroll
    for (int mi = 0; mi < 4; mi++)
        #pragma unroll
        for (int ni = 0; ni < 4; ni++)
            #pragma unroll
            for (int r = 0; r < 4; r++) acc[mi][ni][r] = 0.f;

    for (int k0 = 0; k0 < K; k0 += 32) {
        #pragma unroll
        for (int i = 0; i < 4; i++) {
            int unit = tid + i * 256;            // 0..1023
            // A: 128 rows x 32 cols
            {
                int row = unit >> 3, c4 = (unit & 7) * 4;
                float4 v = *(const float4*)(A + (size_t)(mbase + row) * K + k0 + c4);
                __nv_bfloat16 h0 = __float2bfloat16(v.x);
                __nv_bfloat16 h1 = __float2bfloat16(v.y);
                __nv_bfloat16 h2 = __float2bfloat16(v.z);
                __nv_bfloat16 h3 = __float2bfloat16(v.w);
                uint2 hv; hv.x = pack_bf2(h0, h1); hv.y = pack_bf2(h2, h3);
                *(uint2*)&Ahi[row][c4] = hv;
                uint2 lv;
                lv.x = pack_bf2(__float2bfloat16(v.x - __bfloat162float(h0)),
                                __float2bfloat16(v.y - __bfloat162float(h1)));
                lv.y = pack_bf2(__float2bfloat16(v.z - __bfloat162float(h2)),
                                __float2bfloat16(v.w - __bfloat162float(h3)));
                *(uint2*)&Alo[row][c4] = lv;
            }
            // B: 32 k-rows x 128 n-cols, natural [k][n]
            {
                int kr = unit >> 5, c4 = (unit & 31) * 4;
                float4 v = *(const float4*)(B + (size_t)(k0 + kr) * N + nbase + c4);
                __nv_bfloat16 h0 = __float2bfloat16(v.x);
                __nv_bfloat16 h1 = __float2bfloat16(v.y);
                __nv_bfloat16 h2 = __float2bfloat16(v.z);
                __nv_bfloat16 h3 = __float2bfloat16(v.w);
                uint2 hv; hv.x = pack_bf2(h0, h1); hv.y = pack_bf2(h2, h3);
                *(uint2*)&Bhi[kr][c4] = hv;
                uint2 lv;
                lv.x = pack_bf2(__float2bfloat16(v.x - __bfloat162float(h0)),
                                __float2bfloat16(v.y - __bfloat162float(h1)));
                lv.y = pack_bf2(__float2bfloat16(v.z - __bfloat162float(h2)),
                                __float2bfloat16(v.w - __bfloat162float(h3)));
                *(uint2*)&Blo[kr][c4] = lv;
            }
        }
        __syncthreads();

        #pragma unroll
        for (int s = 0; s < 2; s++) {
            int arow = warpM * 64 + (lane & 15);
            int acol = s * 16 + ((lane >> 4) << 3);
            int bkr  = s * 16 + (lane & 15);          // k row for trans ldmatrix
            int bnc  = warpN * 32;

            uint32_t ah[4][4];
            #pragma unroll
            for (int mi = 0; mi < 4; mi++) {
                uint32_t addr = (uint32_t)__cvta_generic_to_shared(&Ahi[arow + mi*16][acol]);
                asm volatile("ldmatrix.sync.aligned.m8n8.x4.shared.b16 {%0,%1,%2,%3}, [%4];"
                    : "=r"(ah[mi][0]), "=r"(ah[mi][1]), "=r"(ah[mi][2]), "=r"(ah[mi][3])
                    : "r"(addr));
            }
            uint32_t bh[4][2];
            #pragma unroll
            for (int ni = 0; ni < 4; ni++) {
                uint32_t addr = (uint32_t)__cvta_generic_to_shared(&Bhi[bkr][bnc + ni*8]);
                asm volatile("ldmatrix.sync.aligned.m8n8.x2.trans.shared.b16 {%0,%1}, [%2];"
                    : "=r"(bh[ni][0]), "=r"(bh[ni][1]) : "r"(addr));
            }
            // hi * hi
            #pragma unroll
            for (int mi = 0; mi < 4; mi++)
                #pragma unroll
                for (int ni = 0; ni < 4; ni++)
                    asm volatile(
                        "mma.sync.aligned.m16n8k16.row.col.f32.bf16.bf16.f32 "
                        "{%0,%1,%2,%3}, {%4,%5,%6,%7}, {%8,%9}, {%0,%1,%2,%3};"
                        : "+f"(acc[mi][ni][0]), "+f"(acc[mi][ni][1]),
                          "+f"(acc[mi][ni][2]), "+f"(acc[mi][ni][3])
                        : "r"(ah[mi][0]), "r"(ah[mi][1]), "r"(ah[mi][2]), "r"(ah[mi][3]),
                          "r"(bh[ni][0]), "r"(bh[ni][1]));
            // hi * lo
            uint32_t bl[4][2];
            #pragma unroll
            for (int ni = 0; ni < 4; ni++) {
                uint32_t addr = (uint32_t)__cvta_generic_to_shared(&Blo[bkr][bnc + ni*8]);
                asm volatile("ldmatrix.sync.aligned.m8n8.x2.trans.shared.b16 {%0,%1}, [%2];"
                    : "=r"(bl[ni][0]), "=r"(bl[ni][1]) : "r"(addr));
            }
            #pragma unroll
            for (int mi = 0; mi < 4; mi++)
                #pragma unroll
                for (int ni = 0; ni < 4; ni++)
                    asm volatile(
                        "mma.sync.aligned.m16n8k16.row.col.f32.bf16.bf16.f32 "
                        "{%0,%1,%2,%3}, {%4,%5,%6,%7}, {%8,%9}, {%0,%1,%2,%3};"
                        : "+f"(acc[mi][ni][0]), "+f"(acc[mi][ni][1]),
                          "+f"(acc[mi][ni][2]), "+f"(acc[mi][ni][3])
                        : "r"(ah[mi][0]), "r"(ah[mi][1]), "r"(ah[mi][2]), "r"(ah[mi][3]),
                          "r"(bl[ni][0]), "r"(bl[ni][1]));
            // lo * hi
            uint32_t al[4][4];
            #pragma unroll
            for (int mi = 0; mi < 4; mi++) {
                uint32_t addr = (uint32_t)__cvta_generic_to_shared(&Alo[arow + mi*16][acol]);
                asm volatile("ldmatrix.sync.aligned.m8n8.x4.shared.b16 {%0,%1,%2,%3}, [%4];"
                    : "=r"(al[mi][0]), "=r"(al[mi][1]), "=r"(al[mi][2]), "=r"(al[mi][3])
                    : "r"(addr));
            }
            #pragma unroll
            for (int mi = 0; mi < 4; mi++)
                #pragma unroll
                for (int ni = 0; ni < 4; ni++)
                    asm volatile(
                        "mma.sync.aligned.m16n8k16.row.col.f32.bf16.bf16.f32 "
                        "{%0,%1,%2,%3}, {%4,%5,%6,%7}, {%8,%9}, {%0,%1,%2,%3};"
                        : "+f"(acc[mi][ni][0]), "+f"(acc[mi][ni][1]),
                          "+f"(acc[mi][ni][2]), "+f"(acc[mi][ni][3])
                        : "r"(al[mi][0]), "r"(al[mi][1]), "r"(al[mi][2]), "r"(al[mi][3]),
                          "r"(bh[ni][0]), "r"(bh[ni][1]));
        }
        __syncthreads();
    }

    int mrow = mbase + warpM * 64;
    int ncol = nbase + warpN * 32;
    #pragma unroll
    for (int mi = 0; mi < 4; mi++) {
        #pragma unroll
        for (int ni = 0; ni < 4; ni++) {
            int m0 = mrow + mi * 16 + (lane >> 2);
            int n0 = ncol + ni * 8 + 2 * (lane & 3);
            float bx = 0.f, by = 0.f;
            if (bias) { float2 bv = *(const float2*)(bias + n0); bx = bv.x; by = bv.y; }
            float o00 = acc[mi][ni][0] + bx, o01 = acc[mi][ni][1] + by;
            float o10 = acc[mi][ni][2] + bx, o11 = acc[mi][ni][3] + by;
            float* q0 = C + (size_t)m0 * N + n0;
            float* q1 = C + (size_t)(m0 + 8) * N + n0;
            if (flags & FLAG_RESID) {
                float2 r0 = *(const float2*)q0;
                float2 r1 = *(const float2*)q1;
                o00 += r0.x; o01 += r0.y; o10 += r1.x; o11 += r1.y;
            }
            if (flags & FLAG_RELU) {
                o00 = fmaxf(o00, 0.f); o01 = fmaxf(o01, 0.f);
                o10 = fmaxf(o10, 0.f); o11 = fmaxf(o11, 0.f);
            }
            *(float2*)q0 = make_float2(o00, o01);
            *(float2*)q1 = make_float2(o10, o11);
        }
    }
}

// ---------------- attention scores: S = Q @ K^T * scale -------------------
__global__ void __launch_bounds__(256) scores_kernel(float* __restrict__ attn) {
    int kt = blockIdx.x, qt = blockIdx.y;
    if (kt > qt) return;
    int bh = blockIdx.z;
    int b = bh >> 4, h = bh & 15;
    __shared__ float Qs[64][68];
    __shared__ float Ks[64][68];
    int tid = threadIdx.x;
    int lr = tid >> 4;           // 0..15
    int lc = (tid & 15) * 4;     // 0..60
    #pragma unroll
    for (int r = 0; r < 4; r++) {
        int row = r * 16 + lr;
        const float* qp = g_qkv + (size_t)(b*Tn + qt*64 + row) * (3*Dm) + h*HSz + lc;
        float4 qv = *(const float4*)qp;
        Qs[row][lc] = qv.x; Qs[row][lc+1] = qv.y; Qs[row][lc+2] = qv.z; Qs[row][lc+3] = qv.w;
        const float* kp = g_qkv + (size_t)(b*Tn + kt*64 + row) * (3*Dm) + Dm + h*HSz + lc;
        float4 kv = *(const float4*)kp;
        Ks[row][lc] = kv.x; Ks[row][lc+1] = kv.y; Ks[row][lc+2] = kv.z; Ks[row][lc+3] = kv.w;
    }
    __syncthreads();
    int tr = lr * 4, tc = lc;   // 4x4 microtile
    float acc[4][4] = {};
    #pragma unroll
    for (int kk = 0; kk < 64; kk++) {
        float a[4], bb[4];
        #pragma unroll
        for (int i = 0; i < 4; i++) a[i]  = Qs[tr + i][kk];
        #pragma unroll
        for (int j = 0; j < 4; j++) bb[j] = Ks[tc + j][kk];
        #pragma unroll
        for (int i = 0; i < 4; i++)
            #pragma unroll
            for (int j = 0; j < 4; j++) acc[i][j] += a[i] * bb[j];
    }
    float* outp = attn + (size_t)bh * Tn * Tn;
    #pragma unroll
    for (int i = 0; i < 4; i++)
        #pragma unroll
        for (int j = 0; j < 4; j++)
            outp[(size_t)(qt*64 + tr + i) * Tn + kt*64 + tc + j] = acc[i][j] * SCALE;
}

// ---------------- causal softmax in-place over d_out attn rows ------------
__global__ void __launch_bounds__(256) softmax_kernel(float* __restrict__ attn) {
    int t = blockIdx.x, bh = blockIdx.y, tid = threadIdx.x;
    float* row = attn + (size_t)bh * Tn * Tn + (size_t)t * Tn;
    int valid = t + 1;
    float v[4];
    float m = -1e30f;
    #pragma unroll
    for (int i = 0; i < 4; i++) {
        int j = tid + i*256;
        v[i] = row[j];
        if (j < valid) m = fmaxf(m, v[i]);
    }
    __shared__ float red[256];
    red[tid] = m; __syncthreads();
    for (int st = 128; st > 0; st >>= 1) { if (tid < st) red[tid] = fmaxf(red[tid], red[tid+st]); __syncthreads(); }
    m = red[0]; __syncthreads();
    float s = 0.f;
    #pragma unroll
    for (int i = 0; i < 4; i++) {
        int j = tid + i*256;
        float e = (j < valid) ? expf(v[i] - m) : 0.f;
        v[i] = e; s += e;
    }
    red[tid] = s; __syncthreads();
    for (int st = 128; st > 0; st >>= 1) { if (tid < st) red[tid] += red[tid+st]; __syncthreads(); }
    float inv = 1.0f / red[0];
    #pragma unroll
    for (int i = 0; i < 4; i++) row[tid + i*256] = v[i] * inv;
}

// ---------------- O = P @ V (causal k-loop) -------------------------------
// NOTE: attn base is d_out+1 (4 mod 16 bytes) -> scalar loads only.
__global__ void __launch_bounds__(256) av_kernel(const float* __restrict__ attn,
                                                 float* __restrict__ O) {
    int qt = blockIdx.x, bh = blockIdx.y;
    int b = bh >> 4, h = bh & 15;
    __shared__ float Ps[64][68];
    __shared__ float Vs[64][68];
    int tid = threadIdx.x;
    int lr = tid >> 4;
    int lc = (tid & 15) * 4;
    int tr = lr * 4, tc = lc;
    float acc[4][4] = {};
    const float* abase = attn + (size_t)bh * Tn * Tn;
    for (int kt = 0; kt <= qt; kt++) {
        #pragma unroll
        for (int r = 0; r < 4; r++) {
            int row = r * 16 + lr;
            const float* pp = abase + (size_t)(qt*64 + row) * Tn + kt*64 + lc;
            Ps[row][lc]   = pp[0];
            Ps[row][lc+1] = pp[1];
            Ps[row][lc+2] = pp[2];
            Ps[row][lc+3] = pp[3];
            const float* vp = g_qkv + (size_t)(b*Tn + kt*64 + row) * (3*Dm) + 2*Dm + h*HSz + lc;
            float4 vv = *(const float4*)vp;
            Vs[row][lc] = vv.x; Vs[row][lc+1] = vv.y; Vs[row][lc+2] = vv.z; Vs[row][lc+3] = vv.w;
        }
        __syncthreads();
        #pragma unroll
        for (int kk = 0; kk < 64; kk++) {
            float a[4], bb[4];
            #pragma unroll
            for (int i = 0; i < 4; i++) a[i]  = Ps[tr + i][kk];
            #pragma unroll
            for (int j = 0; j < 4; j++) bb[j] = Vs[kk][tc + j];
            #pragma unroll
            for (int i = 0; i < 4; i++)
                #pragma unroll
                for (int j = 0; j < 4; j++) acc[i][j] += a[i] * bb[j];
        }
        __syncthreads();
    }
    #pragma unroll
    for (int i = 0; i < 4; i++)
        #pragma unroll
        for (int j = 0; j < 4; j++)
            O[(size_t)(b*Tn + qt*64 + tr + i) * Dm + h*HSz + tc + j] = acc[i][j];
}

// ---------------- bf16 conversion helpers for the LM head -----------------
__global__ void h2b_kernel() {
    int gid = blockIdx.x * 256 + threadIdx.x;
    g_hb[gid] = __float2bfloat16(g_h[gid]);
}

// Wlm [D,V] row-major -> g_wlmb [V,D] bf16 (tiled transpose)
__global__ void wlm_trans_kernel(const float* __restrict__ W) {
    __shared__ float tile[32][33];
    int v0 = blockIdx.x * 32, d0 = blockIdx.y * 32;
    int tx = threadIdx.x, ty = threadIdx.y;   // 32 x 8
    #pragma unroll
    for (int i = 0; i < 32; i += 8)
        tile[ty + i][tx] = W[(size_t)(d0 + ty + i) * Vn + v0 + tx];
    __syncthreads();
    #pragma unroll
    for (int i = 0; i < 32; i += 8)
        g_wlmb[(size_t)(v0 + ty + i) * Dm + d0 + tx] = __float2bfloat16(tile[tx][ty + i]);
}

// ---------------- bf16 tensor-core LM head (mma.sync) ---------------------
__global__ void __launch_bounds__(256) lm_head_kernel(const float* __restrict__ blm,
                                                      float* __restrict__ Cout) {
    __shared__ __nv_bfloat16 Asm[128][40];
    __shared__ __nv_bfloat16 Bsm[128][40];
    int tid = threadIdx.x;
    int warp = tid >> 5, lane = tid & 31;
    int warpM = warp >> 2, warpN = warp & 3;        // 2 x 4
    int mbase = blockIdx.y * 128, nbase = blockIdx.x * 128;

    float acc[4][4][4];
    #pragma unroll
    for (int mi = 0; mi < 4; mi++)
        #pragma unroll
        for (int ni = 0; ni < 4; ni++)
            #pragma unroll
            for (int r = 0; r < 4; r++) acc[mi][ni][r] = 0.f;

    const __nv_bfloat16* aG = g_hb   + (size_t)mbase * Dm;
    const __nv_bfloat16* bG = g_wlmb + (size_t)nbase * Dm;

    for (int k0 = 0; k0 < Dm; k0 += 32) {
        #pragma unroll
        for (int i = 0; i < 2; i++) {
            int unit = tid + i * 256;          // 0..511
            int row = unit >> 2;
            int ch  = (unit & 3) * 8;          // bf16 column offset
            *(uint4*)&Asm[row][ch] = *(const uint4*)(aG + (size_t)row * Dm + k0 + ch);
            *(uint4*)&Bsm[row][ch] = *(const uint4*)(bG + (size_t)row * Dm + k0 + ch);
        }
        __syncthreads();

        #pragma unroll
        for (int s = 0; s < 2; s++) {
            uint32_t a[4][4];
            #pragma unroll
            for (int mi = 0; mi < 4; mi++) {
                int row = warpM * 64 + mi * 16 + (lane & 15);
                int col = s * 16 + ((lane >> 4) << 3);
                uint32_t addr = (uint32_t)__cvta_generic_to_shared(&Asm[row][col]);
                asm volatile("ldmatrix.sync.aligned.m8n8.x4.shared.b16 {%0,%1,%2,%3}, [%4];"
                    : "=r"(a[mi][0]), "=r"(a[mi][1]), "=r"(a[mi][2]), "=r"(a[mi][3])
                    : "r"(addr));
            }
            uint32_t bf[4][2];
            #pragma unroll
            for (int ni = 0; ni < 4; ni++) {
                int row = warpN * 32 + ni * 8 + (lane & 7);
                int col = s * 16 + (((lane >> 3) & 1) << 3);
                uint32_t addr = (uint32_t)__cvta_generic_to_shared(&Bsm[row][col]);
                asm volatile("ldmatrix.sync.aligned.m8n8.x2.shared.b16 {%0,%1}, [%2];"
                    : "=r"(bf[ni][0]), "=r"(bf[ni][1]) : "r"(addr));
            }
            #pragma unroll
            for (int mi = 0; mi < 4; mi++)
                #pragma unroll
                for (int ni = 0; ni < 4; ni++)
                    asm volatile(
                        "mma.sync.aligned.m16n8k16.row.col.f32.bf16.bf16.f32 "
                        "{%0,%1,%2,%3}, {%4,%5,%6,%7}, {%8,%9}, {%0,%1,%2,%3};"
                        : "+f"(acc[mi][ni][0]), "+f"(acc[mi][ni][1]),
                          "+f"(acc[mi][ni][2]), "+f"(acc[mi][ni][3])
                        : "r"(a[mi][0]), "r"(a[mi][1]), "r"(a[mi][2]), "r"(a[mi][3]),
                          "r"(bf[ni][0]), "r"(bf[ni][1]));
        }
        __syncthreads();
    }

    int mrow = mbase + warpM * 64;
    int ncol = nbase + warpN * 32;
    #pragma unroll
    for (int mi = 0; mi < 4; mi++) {
        #pragma unroll
        for (int ni = 0; ni < 4; ni++) {
            int m0 = mrow + mi * 16 + (lane >> 2);
            int n0 = ncol + ni * 8 + 2 * (lane & 3);
            float2 bv = *(const float2*)(blm + n0);
            float2 o0 = { acc[mi][ni][0] + bv.x, acc[mi][ni][1] + bv.y };
            float2 o1 = { acc[mi][ni][2] + bv.x, acc[mi][ni][3] + bv.y };
            *(float2*)(Cout + (size_t)m0 * Vn + n0)       = o0;
            *(float2*)(Cout + (size_t)(m0 + 8) * Vn + n0) = o1;
        }
    }
}

// ---------------- per-row NLL over 32000-way logits -----------------------
__global__ void __launch_bounds__(512) nll_kernel(const int* __restrict__ targets) {
    int row = blockIdx.x, tid = threadIdx.x;
    const float* lr = g_logits + (size_t)row * Vn;
    float m = -1e30f;
    for (int j = tid; j < Vn; j += 512) m = fmaxf(m, lr[j]);
    __shared__ float red[512];
    red[tid] = m; __syncthreads();
    for (int st = 256; st > 0; st >>= 1) { if (tid < st) red[tid] = fmaxf(red[tid], red[tid+st]); __syncthreads(); }
    m = red[0]; __syncthreads();
    float s = 0.f;
    for (int j = tid; j < Vn; j += 512) s += expf(lr[j] - m);
    red[tid] = s; __syncthreads();
    for (int st = 256; st > 0; st >>= 1) { if (tid < st) red[tid] += red[tid+st]; __syncthreads(); }
    if (tid == 0) {
        int tg = targets[row];
        g_nll[row] = -(lr[tg] - m - logf(red[0]));
    }
}

__global__ void __launch_bounds__(256) loss_reduce_kernel(float* __restrict__ out) {
    int tid = threadIdx.x;
    float s = 0.f;
    for (int i = tid; i < BT; i += 256) s += g_nll[i];
    __shared__ float red[256];
    red[tid] = s; __syncthreads();
    for (int st = 128; st > 0; st >>= 1) { if (tid < st) red[tid] += red[tid+st]; __syncthreads(); }
    if (tid == 0) out[0] = red[0] / (float)BT;
}

// ---------------- launch ---------------------------------------------------
extern "C" void kernel_launch(void* const* d_in, const int* in_sizes, int n_in,
                              void* d_out, int out_size) {
    const int*   idx     = (const int*)  d_in[0];
    const int*   targets = (const int*)  d_in[1];
    const float* tok     = (const float*)d_in[2];
    const float* pos     = (const float*)d_in[3];
    const float* ln1_g   = (const float*)d_in[4];
    const float* ln1_b   = (const float*)d_in[5];
    const float* Wq      = (const float*)d_in[6];
    const float* Wk      = (const float*)d_in[7];
    const float* Wv      = (const float*)d_in[8];
    const float* Wp      = (const float*)d_in[9];
    const float* bp      = (const float*)d_in[10];
    const float* ln2_g   = (const float*)d_in[11];
    const float* ln2_b   = (const float*)d_in[12];
    const float* W1      = (const float*)d_in[13];
    const float* b1      = (const float*)d_in[14];
    const float* W2      = (const float*)d_in[15];
    const float* b2      = (const float*)d_in[16];
    const float* lnf_g   = (const float*)d_in[17];
    const float* lnf_b   = (const float*)d_in[18];
    const float* Wlm     = (const float*)d_in[19];
    const float* blm     = (const float*)d_in[20];

    float* out = (float*)d_out;
    float* attn_all = out + 1;   // (loss, attn) flattened

    float *px, *ph, *pqkv, *po, *pffn, *pwt, *plogits;
    cudaGetSymbolAddress((void**)&px,      g_x);
    cudaGetSymbolAddress((void**)&ph,      g_h);
    cudaGetSymbolAddress((void**)&pqkv,    g_qkv);
    cudaGetSymbolAddress((void**)&po,      g_o);
    cudaGetSymbolAddress((void**)&pffn,    g_ffn);
    cudaGetSymbolAddress((void**)&pwt,     g_wt);
    cudaGetSymbolAddress((void**)&plogits, g_logits);

    embed_kernel<<<(BT*Dm)/256, 256>>>(idx, tok, pos);

    for (int l = 0; l < Ln; l++) {
        float* attn_l = attn_all + (size_t)l * Bsz * Hn * Tn * Tn;
        size_t woff = (size_t)l * Hn * Dm * HSz;

        ln_kernel<<<BT, 256>>>(px, ln1_g + l*Dm, ln1_b + l*Dm, ph);
        wtrans_kernel<<<(Dm*Dm)/256, 256>>>(Wq + woff, Wk + woff, Wv + woff);
        gemm_x3_kernel<<<dim3(3*Dm/128, BT/128), 256>>>(ph, pwt, nullptr, pqkv,
                                                        BT, 3*Dm, Dm, 0);
        scores_kernel<<<dim3(Tn/64, Tn/64, Bsz*Hn), 256>>>(attn_l);
        softmax_kernel<<<dim3(Tn, Bsz*Hn), 256>>>(attn_l);
        av_kernel<<<dim3(Tn/64, Bsz*Hn), 256>>>(attn_l, po);
        gemm_x3_kernel<<<dim3(Dm/128, BT/128), 256>>>(po, Wp + (size_t)l*Dm*Dm,
                                                      bp + l*Dm, px,
                                                      BT, Dm, Dm, FLAG_RESID);
        ln_kernel<<<BT, 256>>>(px, ln2_g + l*Dm, ln2_b + l*Dm, ph);
        gemm_x3_kernel<<<dim3(FFn/128, BT/128), 256>>>(ph, W1 + (size_t)l*Dm*FFn,
                                                       b1 + l*FFn, pffn,
                                                       BT, FFn, Dm, FLAG_RELU);
        gemm_x3_kernel<<<dim3(Dm/128, BT/128), 256>>>(pffn, W2 + (size_t)l*FFn*Dm,
                                                      b2 + l*Dm, px,
                                                      BT, Dm, FFn, FLAG_RESID);
    }

    ln_kernel<<<BT, 256>>>(px, lnf_g, lnf_b, ph);
    h2b_kernel<<<(BT*Dm)/256, 256>>>();
    wlm_trans_kernel<<<dim3(Vn/32, Dm/32), dim3(32, 8)>>>(Wlm);
    lm_head_kernel<<<dim3(Vn/128, BT/128), 256>>>(blm, plogits);
    nll_kernel<<<BT, 512>>>(targets);
    loss_reduce_kernel<<<1, 256>>>(out);
}